// round 11
// baseline (speedup 1.0000x reference)
#include <cuda_runtime.h>
#include <cstdint>

// ---------------- device-global scratch ----------------
__device__ float g_WG1t[1024 * 512];    // [Whx^T ; Wo_up^T] tf32 [n][k]
__device__ float g_Wot2[512 * 512];     // Wo_low^T tf32 [n][k]
__device__ float g_WRt[1536 * 512];     // [W^T ; W2^T ; W3^T] tf32 [n][k]
__device__ float g_WCt[1024 * 512];     // [W4^T ; W8^T] tf32 [n][k]
__device__ float g_Whh[512 * 512];      // W fp32
__device__ float g_W2[512 * 512];
__device__ float g_W3[512 * 512];
__device__ float g_W4[512 * 512];
__device__ float g_W8[512 * 512];
__device__ float g_bG1[1024];           // [bh | bo]
__device__ float g_xr[(size_t)65536 * 512];     // tf32-rounded x [b*256+t][k]
__device__ float g_preh[(size_t)65536 * 512];   // [t*256+b][n] tf32-rounded
__device__ float g_oxp[(size_t)65536 * 512];    // x-part of out logits (+bo), fp32, t-major
__device__ float g_Hall[(size_t)257 * 131072];  // [t][b][n] tf32-rounded
__device__ float g_Q0[(size_t)16384 * 512];     // Q4
__device__ float g_Q1[(size_t)16384 * 512];     // R1
__device__ float g_Q2[(size_t)16384 * 512];     // R2
__device__ float g_Q3[(size_t)8192 * 512];      // Q8 (fp32)
__device__ int g_cnt, g_phase;

// ---------------- helpers ----------------
__device__ __forceinline__ uint32_t smem_u32(const void* p) {
    uint32_t a;
    asm("{ .reg .u64 t; cvta.to.shared.u64 t, %1; cvt.u32.u64 %0, t; }" : "=r"(a) : "l"(p));
    return a;
}
__device__ __forceinline__ float rna_tf32(float x) {
    uint32_t r; asm("cvt.rna.tf32.f32 %0, %1;" : "=r"(r) : "f"(x));
    return __uint_as_float(r);
}
// 0 id, 1 (b,t)swap, 2 chunk4 off, 3 chunk2 off
__device__ __forceinline__ int rowmap(int mode, int off, int m) {
    if (mode == 1) return ((m & 255) << 8) | (m >> 8);
    if (mode == 2) return ((m >> 8) << 10) + (off << 8) + (m & 255);
    if (mode == 3) return ((m >> 8) << 9) + (off << 8) + (m & 255);
    return m;
}
__device__ __forceinline__ void mma8(float* c, const uint32_t* a, const uint32_t* b) {
    asm volatile("mma.sync.aligned.m16n8k8.row.col.f32.tf32.tf32.f32 "
        "{%0,%1,%2,%3}, {%4,%5,%6,%7}, {%8,%9}, {%0,%1,%2,%3};"
        : "+f"(c[0]), "+f"(c[1]), "+f"(c[2]), "+f"(c[3])
        : "r"(a[0]), "r"(a[1]), "r"(a[2]), "r"(a[3]), "r"(b[0]), "r"(b[1]));
}
#define CP16(dst, src) asm volatile("cp.async.cg.shared.global [%0], [%1], 16;" :: "r"(dst), "l"(src))
#define LDSM4(r0, r1, r2, r3, addr)                                              \
    asm volatile("ldmatrix.sync.aligned.m8n8.x4.shared.b16 {%0,%1,%2,%3}, [%4];" \
        : "=r"(r0), "=r"(r1), "=r"(r2), "=r"(r3) : "r"(addr))
#define COMMIT() asm volatile("cp.async.commit_group;")
#define WAIT2()  asm volatile("cp.async.wait_group 2;")

// ---------------- prep ----------------
__global__ void prep_kernel(const float* __restrict__ Wh, const float* __restrict__ bh,
                            const float* __restrict__ Wo, const float* __restrict__ bo,
                            const float* __restrict__ h0) {
    int i = blockIdx.x * blockDim.x + threadIdx.x;
    if (i == 0) { g_cnt = 0; g_phase = 0; }
    if (i < 524288) {                       // WG1t [n=1024][k=512]
        int n = i >> 9, k = i & 511;
        g_WG1t[i] = rna_tf32(n < 512 ? Wh[k * 512 + n] : Wo[k * 512 + (n - 512)]);
    }
    if (i < 262144) {
        int n = i >> 9, k = i & 511;
        g_Wot2[i] = rna_tf32(Wo[(size_t)(k + 512) * 512 + n]);   // Wo lower half ^T
        float w = Wh[262144 + i];                                 // W_hh [k][n], i=k*512+n
        g_Whh[i] = w;
        g_WRt[i] = rna_tf32(Wh[(size_t)(512 + k) * 512 + n]);    // W^T block0
    }
    if (i < 131072) g_Hall[i] = rna_tf32(h0[i]);
    if (i < 1024) g_bG1[i] = (i < 512) ? bh[i] : bo[i - 512];
}

__global__ void xr_kernel(const float* __restrict__ x) {
    size_t i = ((size_t)blockIdx.x * blockDim.x + threadIdx.x) * 4;
    float4 v = *(const float4*)(x + i);
    v.x = rna_tf32(v.x); v.y = rna_tf32(v.y);
    v.z = rna_tf32(v.z); v.w = rna_tf32(v.w);
    *(float4*)(g_xr + i) = v;
}

// ------------- fp32 512^3 GEMM (squarings), 32x64 tile, grid(8,16) -------------
__global__ __launch_bounds__(256) void sq512(const float* __restrict__ A,
                                             const float* __restrict__ B,
                                             float* __restrict__ C,
                                             float* __restrict__ Ct) {
    __shared__ float As[16][36];
    __shared__ float Bs[16][64];
    const int tid = threadIdx.x;
    const int bm = blockIdx.y * 32, bn = blockIdx.x * 64;
    const int tx = tid & 15, ty = tid >> 4;
    const int ar = tid >> 3, ac2 = (tid & 7) * 2;
    const int br = tid >> 4, bc4 = (tid & 15) * 4;

    float acc[2][4] = {{0, 0, 0, 0}, {0, 0, 0, 0}};
    for (int k0 = 0; k0 < 512; k0 += 16) {
        float2 va = *(const float2*)(A + (size_t)(bm + ar) * 512 + k0 + ac2);
        float4 vb = *(const float4*)(B + (size_t)(k0 + br) * 512 + bn + bc4);
        __syncthreads();
        As[ac2 + 0][ar] = va.x;
        As[ac2 + 1][ar] = va.y;
        *(float4*)(&Bs[br][bc4]) = vb;
        __syncthreads();
#pragma unroll
        for (int kk = 0; kk < 16; kk++) {
            float a0 = As[kk][ty * 2 + 0], a1 = As[kk][ty * 2 + 1];
#pragma unroll
            for (int j = 0; j < 4; j++) {
                float b = Bs[kk][tx * 4 + j];
                acc[0][j] += a0 * b;
                acc[1][j] += a1 * b;
            }
        }
    }
#pragma unroll
    for (int i = 0; i < 2; i++) {
        int m = bm + ty * 2 + i;
        float4 v = {acc[i][0], acc[i][1], acc[i][2], acc[i][3]};
        *(float4*)(C + (size_t)m * 512 + bn + tx * 4) = v;
#pragma unroll
        for (int j = 0; j < 4; j++)
            Ct[(size_t)(bn + tx * 4 + j) * 512 + m] = rna_tf32(acc[i][j]);
    }
}

// ---------------- tf32 mma GEMM, 128x128 tile, K=512, 4-stage pipeline ----------
// MODE 0 (G1'): O split: col<512 -> rna(+bh)->preh[r]; col>=512 -> fp32(+bo)->oxp[r]
// MODE 1 (G2'): O = sigmoid(acc + oxp[swap(r)])  -> out
// MODE 2: O = (+Add[addmap]) (rna if rnd)
// MODE 4 (recovery): blk=bn>>9; Add in {preh[4j], Q1[j], Q2[j]}; O=Hall[4j+blk+1] rna
template <int MODE>
__global__ __launch_bounds__(256, 2) void mma_gemm(
    const float* __restrict__ A0, int amap, int aoff,
    const float* __restrict__ Add, int addmap, int addoff,
    float* __restrict__ O,
    const float* __restrict__ Bt, int rnd) {
    extern __shared__ float sm[];
    float* Asg = sm;            // 4 x 2560 floats
    float* Bsg = sm + 10240;

    const int tid = threadIdx.x;
    const int lane = tid & 31;
    const int wid = tid >> 5;
    const int wm = (wid >> 2) * 64;
    const int wn = (wid & 3) * 32;
    const int bm = blockIdx.y * 128;
    const int bn = blockIdx.x * 128;
    const int ar1 = tid >> 2, ac = (tid & 3) * 4;

    const float* aP[2];
#pragma unroll
    for (int h = 0; h < 2; h++) {
        int gm = bm + ar1 + h * 64;
        aP[h] = A0 + (size_t)rowmap(amap, aoff, gm) * 512 + ac;
    }
    const float* bP = Bt + (size_t)(bn + ar1) * 512 + ac;

    auto issue = [&](int it) {
        if (it < 32) {
            const int k0 = it * 16;
            float* Ast = Asg + (it & 3) * 2560;
            float* Bst = Bsg + (it & 3) * 2560;
#pragma unroll
            for (int h = 0; h < 2; h++) {
                CP16(smem_u32(Ast + (ar1 + h * 64) * 20 + ac), aP[h] + k0);
                CP16(smem_u32(Bst + (ar1 + h * 64) * 20 + ac), bP + (size_t)h * 64 * 512 + k0);
            }
        }
        COMMIT();
    };

    const int rA = ((lane >> 3) & 1) * 8 + (lane & 7);
    const int cA = ((lane >> 4) & 1) * 4;
    const int rB = ((lane >> 4) & 1) * 8 + (lane & 7);
    const int cB = ((lane >> 3) & 1) * 4;
    uint32_t baseA[4], baseB[4];
#pragma unroll
    for (int s = 0; s < 4; s++) {
        baseA[s] = smem_u32(Asg + s * 2560 + (wm + rA) * 20 + cA);
        baseB[s] = smem_u32(Bsg + s * 2560 + (wn + rB) * 20 + cB);
    }

    float acc[4][4][4];
#pragma unroll
    for (int a = 0; a < 4; a++)
#pragma unroll
        for (int b = 0; b < 4; b++)
#pragma unroll
            for (int c = 0; c < 4; c++) acc[a][b][c] = 0.f;

    issue(0); issue(1); issue(2);
    for (int it = 0; it < 32; it++) {
        WAIT2();
        __syncthreads();
        issue(it + 3);
        const int buf = it & 3;
#pragma unroll
        for (int kk = 0; kk < 2; kk++) {
            uint32_t af[4][4], bf[2][4];
#pragma unroll
            for (int mf = 0; mf < 4; mf++)
                LDSM4(af[mf][0], af[mf][1], af[mf][2], af[mf][3],
                      baseA[buf] + mf * 1280 + kk * 32);
#pragma unroll
            for (int p = 0; p < 2; p++)
                LDSM4(bf[p][0], bf[p][1], bf[p][2], bf[p][3],
                      baseB[buf] + p * 1280 + kk * 32);
#pragma unroll
            for (int mf = 0; mf < 4; mf++)
#pragma unroll
                for (int p = 0; p < 2; p++) {
                    mma8(acc[mf][2 * p + 0], af[mf], &bf[p][0]);
                    mma8(acc[mf][2 * p + 1], af[mf], &bf[p][2]);
                }
        }
    }

    const int blk = bn >> 9;
#pragma unroll
    for (int mf = 0; mf < 4; mf++)
#pragma unroll
        for (int nf = 0; nf < 4; nf++) {
            int col = bn + wn + nf * 8 + (lane & 3) * 2;
            int lc = col & 511;
#pragma unroll
            for (int h = 0; h < 2; h++) {
                int r = bm + wm + mf * 16 + (lane >> 2) + h * 8;
                float c0 = acc[mf][nf][h * 2 + 0];
                float c1 = acc[mf][nf][h * 2 + 1];
                float2 v;
                if (MODE == 0) {
                    c0 += g_bG1[col];
                    c1 += g_bG1[col + 1];
                    if (blk == 0) {
                        v.x = rna_tf32(c0); v.y = rna_tf32(c1);
                        *(float2*)(g_preh + (size_t)r * 512 + lc) = v;
                    } else {
                        v.x = c0; v.y = c1;
                        *(float2*)(g_oxp + (size_t)r * 512 + lc) = v;
                    }
                } else if (MODE == 1) {
                    const float* ox = g_oxp + (size_t)rowmap(1, 0, r) * 512 + lc;
                    v.x = 1.f / (1.f + __expf(-(c0 + ox[0])));
                    v.y = 1.f / (1.f + __expf(-(c1 + ox[1])));
                    *(float2*)(O + (size_t)r * 512 + lc) = v;
                } else if (MODE == 2) {
                    const float* ap = Add + (size_t)rowmap(addmap, addoff, r) * 512 + lc;
                    c0 += ap[0]; c1 += ap[1];
                    if (rnd) { v.x = rna_tf32(c0); v.y = rna_tf32(c1); }
                    else { v.x = c0; v.y = c1; }
                    *(float2*)(O + (size_t)r * 512 + lc) = v;
                } else {  // MODE 4: recovery
                    int p0 = ((r >> 8) << 10) + (r & 255);
                    const float* ap;
                    if (blk == 0)      ap = g_preh + (size_t)p0 * 512 + lc;
                    else if (blk == 1) ap = g_Q1 + (size_t)r * 512 + lc;
                    else               ap = g_Q2 + (size_t)r * 512 + lc;
                    v.x = rna_tf32(c0 + ap[0]);
                    v.y = rna_tf32(c1 + ap[1]);
                    *(float2*)(g_Hall + (size_t)(p0 + ((blk + 1) << 8)) * 512 + lc) = v;
                }
            }
        }
}

// ---------------- persistent tensor-core scan, 4-stage pipeline ----------------
__device__ __forceinline__ void gbar(int target) {
    __syncthreads();
    if (threadIdx.x == 0) {
        __threadfence();
        int old = atomicAdd(&g_cnt, 1);
        if (old == 63) {
            g_cnt = 0;
            __threadfence();
            atomicExch(&g_phase, target);
        } else {
            while (atomicAdd(&g_phase, 0) < target) {}
        }
    }
    __syncthreads();
}

__global__ __launch_bounds__(256) void scan_kernel(const float* __restrict__ q4,
                                                   const float* __restrict__ q8,
                                                   float* __restrict__ outp) {
    extern __shared__ float sm[];
    float* Asg = sm;           // 4 x 640
    float* Bsg = sm + 2560;    // 4 x 2560
    const int tid = threadIdx.x;
    const int lane = tid & 31;
    const int wid = tid >> 5;
    const int wm = (wid >> 2) * 16;
    const int wn = (wid & 3) * 32;
    const int bn = blockIdx.x * 128;
    const int bm = blockIdx.y * 32;
    const int aar = tid >> 2, aac = (tid & 3) * 4;
    const int br = tid >> 2, bc = (tid & 3) * 4;
    const float* bP = g_WCt + (size_t)(bn + br) * 512 + bc;

    const int rA = ((lane >> 3) & 1) * 8 + (lane & 7);
    const int cA = ((lane >> 4) & 1) * 4;
    const int rB = ((lane >> 4) & 1) * 8 + (lane & 7);
    const int cB = ((lane >> 3) & 1) * 4;
    uint32_t baseA[4], baseB[4];
#pragma unroll
    for (int s = 0; s < 4; s++) {
        baseA[s] = smem_u32(Asg + s * 640 + (wm + rA) * 20 + cA);
        baseB[s] = smem_u32(Bsg + s * 2560 + (wn + rB) * 20 + cB);
    }

    for (int k = 0; k < 32; k++) {
        const float* hsrc = g_Hall + (size_t)(8 * k) * 131072;

        auto issue = [&](int it) {
            if (it < 32) {
                const int k0 = it * 16;
                float* Ast = Asg + (it & 3) * 640;
                float* Bst = Bsg + (it & 3) * 2560;
                if (tid < 128)
                    CP16(smem_u32(Ast + aar * 20 + aac),
                         hsrc + (size_t)(bm + aar) * 512 + k0 + aac);
#pragma unroll
                for (int h = 0; h < 2; h++)
                    CP16(smem_u32(Bst + (br + h * 64) * 20 + bc),
                         bP + (size_t)h * 64 * 512 + k0);
            }
            COMMIT();
        };

        float acc[4][4];
#pragma unroll
        for (int a = 0; a < 4; a++)
#pragma unroll
            for (int b = 0; b < 4; b++) acc[a][b] = 0.f;

        issue(0); issue(1); issue(2);
        for (int it = 0; it < 32; it++) {
            WAIT2();
            __syncthreads();
            issue(it + 3);
            const int buf = it & 3;
#pragma unroll
            for (int kk = 0; kk < 2; kk++) {
                uint32_t af[4], bf[2][4];
                LDSM4(af[0], af[1], af[2], af[3], baseA[buf] + kk * 32);
#pragma unroll
                for (int p = 0; p < 2; p++)
                    LDSM4(bf[p][0], bf[p][1], bf[p][2], bf[p][3],
                          baseB[buf] + p * 1280 + kk * 32);
#pragma unroll
                for (int p = 0; p < 2; p++) {
                    mma8(acc[2 * p + 0], af, &bf[p][0]);
                    mma8(acc[2 * p + 1], af, &bf[p][2]);
                }
            }
        }

#pragma unroll
        for (int nf = 0; nf < 4; nf++) {
            int col = bn + wn + nf * 8 + (lane & 3) * 2;
#pragma unroll
            for (int h = 0; h < 2; h++) {
                int r = bm + wm + (lane >> 2) + h * 8;
                float c0 = acc[nf][h * 2 + 0];
                float c1 = acc[nf][h * 2 + 1];
                size_t off = (size_t)r * 512;
                if (bn < 512) {
                    const float* p = q4 + (size_t)(2 * k) * 131072 + off + col;
                    float2 v = {rna_tf32(c0 + p[0]), rna_tf32(c1 + p[1])};
                    *(float2*)(g_Hall + (size_t)(8 * k + 4) * 131072 + off + col) = v;
                } else {
                    int c2 = col - 512;
                    const float* p = q8 + (size_t)k * 131072 + off + c2;
                    float f0 = c0 + p[0], f1 = c1 + p[1];
                    float2 v = {rna_tf32(f0), rna_tf32(f1)};
                    *(float2*)(g_Hall + (size_t)(8 * k + 8) * 131072 + off + c2) = v;
                    if (k == 31) {
                        float2 w = {f0, f1};
                        *(float2*)(outp + (size_t)33554432 + off + c2) = w;
                    }
                }
            }
        }
        gbar(k + 1);
    }
}

// ---------------- launch ----------------
extern "C" void kernel_launch(void* const* d_in, const int* in_sizes, int n_in,
                              void* d_out, int out_size) {
    const float* x  = (const float*)d_in[0];
    const float* h0 = (const float*)d_in[1];
    const float* Wh = (const float*)d_in[2];
    const float* bh = (const float*)d_in[3];
    const float* Wo = (const float*)d_in[4];
    const float* bo = (const float*)d_in[5];
    float* out = (float*)d_out;

    float *xr, *preh, *hall, *q0, *q1, *q2, *q3;
    float *whh, *w2, *w3, *w4, *w8, *wg1t, *wot2, *wrt, *wct;
    cudaGetSymbolAddress((void**)&xr, g_xr);
    cudaGetSymbolAddress((void**)&preh, g_preh);
    cudaGetSymbolAddress((void**)&hall, g_Hall);
    cudaGetSymbolAddress((void**)&q0, g_Q0);
    cudaGetSymbolAddress((void**)&q1, g_Q1);
    cudaGetSymbolAddress((void**)&q2, g_Q2);
    cudaGetSymbolAddress((void**)&q3, g_Q3);
    cudaGetSymbolAddress((void**)&whh, g_Whh);
    cudaGetSymbolAddress((void**)&w2, g_W2);
    cudaGetSymbolAddress((void**)&w3, g_W3);
    cudaGetSymbolAddress((void**)&w4, g_W4);
    cudaGetSymbolAddress((void**)&w8, g_W8);
    cudaGetSymbolAddress((void**)&wg1t, g_WG1t);
    cudaGetSymbolAddress((void**)&wot2, g_Wot2);
    cudaGetSymbolAddress((void**)&wrt, g_WRt);
    cudaGetSymbolAddress((void**)&wct, g_WCt);

    const int MMA_SMEM = 81920;
    const int SCAN_SMEM = 51200;
    cudaFuncSetAttribute(mma_gemm<0>, cudaFuncAttributeMaxDynamicSharedMemorySize, MMA_SMEM);
    cudaFuncSetAttribute(mma_gemm<1>, cudaFuncAttributeMaxDynamicSharedMemorySize, MMA_SMEM);
    cudaFuncSetAttribute(mma_gemm<2>, cudaFuncAttributeMaxDynamicSharedMemorySize, MMA_SMEM);
    cudaFuncSetAttribute(mma_gemm<4>, cudaFuncAttributeMaxDynamicSharedMemorySize, MMA_SMEM);
    cudaFuncSetAttribute(scan_kernel, cudaFuncAttributeMaxDynamicSharedMemorySize, SCAN_SMEM);

    prep_kernel<<<2048, 256>>>(Wh, bh, Wo, bo, h0);
    xr_kernel<<<32768, 256>>>(x);
    // matrix powers (fp32) + rounded transposes into WRt / WCt
    sq512<<<dim3(8, 16), 256>>>(whh, whh, w2, wrt + 262144);   // W2, W2^T
    sq512<<<dim3(8, 16), 256>>>(w2, whh, w3, wrt + 524288);    // W3, W3^T
    sq512<<<dim3(8, 16), 256>>>(w2, w2, w4, wct);              // W4, W4^T
    sq512<<<dim3(8, 16), 256>>>(w4, w4, w8, wct + 262144);     // W8, W8^T

    // G1': [preh | oxp] = xr(b,t-gather) @ [Whx^T ; Wo_up^T] + [bh|bo]
    mma_gemm<0><<<dim3(8, 512), 256, MMA_SMEM>>>(xr, 1, 0, nullptr, 0, 0,
                                                 nullptr, wg1t, 1);
    // Horner: R1 = preh(0)@W + preh(1); R2 = R1@W + preh(2); Q4 = R2@W + preh(3)
    mma_gemm<2><<<dim3(4, 128), 256, MMA_SMEM>>>(preh, 2, 0, preh, 2, 1, q1, wrt, 1);
    mma_gemm<2><<<dim3(4, 128), 256, MMA_SMEM>>>(q1, 0, 0, preh, 2, 2, q2, wrt, 1);
    mma_gemm<2><<<dim3(4, 128), 256, MMA_SMEM>>>(q2, 0, 0, preh, 2, 3, q0, wrt, 1);
    // Q8[k] = Q4[2k]@W4 + Q4[2k+1]   (fp32 output, Add-only consumer)
    mma_gemm<2><<<dim3(4, 64), 256, MMA_SMEM>>>(q0, 3, 0, q0, 3, 1, q3, wct, 0);
    // persistent scan (writes out tail at k=31)
    scan_kernel<<<dim3(8, 8), 256, SCAN_SMEM>>>(q0, q3, out);
    // single recovery GEMM: Hall[4j+i] = Hall[4j]@W^i + {preh[4j], R1, R2}
    mma_gemm<4><<<dim3(12, 128), 256, MMA_SMEM>>>(hall, 2, 0, nullptr, 0, 0,
                                                  nullptr, wrt, 1);
    // G2': out = sigmoid(Hall-gather @ Wo_low^T + oxp)
    mma_gemm<1><<<dim3(4, 512), 256, MMA_SMEM>>>(hall, 1, 0, nullptr, 0, 0,
                                                 out, wot2, 0);
}

// round 12
// speedup vs baseline: 1.1019x; 1.1019x over previous
#include <cuda_runtime.h>
#include <cstdint>

// ---------------- device-global scratch ----------------
__device__ float g_W1t[512 * 512];      // W_hx^T [n][k] tf32
__device__ float g_WRt[1536 * 512];     // [W^T ; W2^T ; W3^T] tf32 [n][k]
__device__ float g_WCt[1024 * 512];     // [W4^T ; W8^T] tf32 [n][k]
__device__ float g_Whh[512 * 512];      // W fp32
__device__ float g_W2[512 * 512];
__device__ float g_W3[512 * 512];
__device__ float g_W4[512 * 512];
__device__ float g_W8[512 * 512];
__device__ float g_Wot[512 * 1024];     // W_o^T [n][k] tf32
__device__ float g_bh[512];
__device__ float g_bo[512];
__device__ float g_xr[(size_t)65536 * 512];     // tf32-rounded x [b*256+t][k]
__device__ float g_preh[(size_t)65536 * 512];   // [t*256+b][n] tf32-rounded
__device__ float g_Hall[(size_t)257 * 131072];  // [t][b][n] tf32-rounded
__device__ float g_Q0[(size_t)16384 * 512];     // Q4
__device__ float g_Q1[(size_t)16384 * 512];     // R1
__device__ float g_Q2[(size_t)16384 * 512];     // R2
__device__ float g_Q3[(size_t)8192 * 512];      // Q8 (fp32)
__device__ int g_cnt, g_phase;

// ---------------- helpers ----------------
__device__ __forceinline__ uint32_t smem_u32(const void* p) {
    uint32_t a;
    asm("{ .reg .u64 t; cvta.to.shared.u64 t, %1; cvt.u32.u64 %0, t; }" : "=r"(a) : "l"(p));
    return a;
}
__device__ __forceinline__ float rna_tf32(float x) {
    uint32_t r; asm("cvt.rna.tf32.f32 %0, %1;" : "=r"(r) : "f"(x));
    return __uint_as_float(r);
}
// 0 id, 1 (b,t)swap, 2 chunk4 off, 3 chunk2 off
__device__ __forceinline__ int rowmap(int mode, int off, int m) {
    if (mode == 1) return ((m & 255) << 8) | (m >> 8);
    if (mode == 2) return ((m >> 8) << 10) + (off << 8) + (m & 255);
    if (mode == 3) return ((m >> 8) << 9) + (off << 8) + (m & 255);
    return m;
}
__device__ __forceinline__ void mma8(float* c, const uint32_t* a, const uint32_t* b) {
    asm volatile("mma.sync.aligned.m16n8k8.row.col.f32.tf32.tf32.f32 "
        "{%0,%1,%2,%3}, {%4,%5,%6,%7}, {%8,%9}, {%0,%1,%2,%3};"
        : "+f"(c[0]), "+f"(c[1]), "+f"(c[2]), "+f"(c[3])
        : "r"(a[0]), "r"(a[1]), "r"(a[2]), "r"(a[3]), "r"(b[0]), "r"(b[1]));
}
#define CP16(dst, src) asm volatile("cp.async.cg.shared.global [%0], [%1], 16;" :: "r"(dst), "l"(src))
#define LDSM4(r0, r1, r2, r3, addr)                                              \
    asm volatile("ldmatrix.sync.aligned.m8n8.x4.shared.b16 {%0,%1,%2,%3}, [%4];" \
        : "=r"(r0), "=r"(r1), "=r"(r2), "=r"(r3) : "r"(addr))
#define COMMIT() asm volatile("cp.async.commit_group;")
#define WAIT2()  asm volatile("cp.async.wait_group 2;")

// ---------------- prep ----------------
__global__ void prep_kernel(const float* __restrict__ Wh, const float* __restrict__ bh,
                            const float* __restrict__ Wo, const float* __restrict__ bo,
                            const float* __restrict__ h0) {
    int i = blockIdx.x * blockDim.x + threadIdx.x;
    if (i == 0) { g_cnt = 0; g_phase = 0; }
    if (i < 524288) {                       // Wo [1024][512] -> Wot [n][k=1024]
        int k = i >> 9, n = i & 511;
        g_Wot[n * 1024 + k] = rna_tf32(Wo[i]);
    }
    if (i < 262144) {
        int k = i >> 9, n = i & 511;
        g_W1t[n * 512 + k] = rna_tf32(Wh[i]);
        float w = Wh[262144 + i];
        g_Whh[i] = w;
        g_WRt[n * 512 + k] = rna_tf32(w);   // W^T block 0 of WRt
    }
    if (i < 131072) g_Hall[i] = rna_tf32(h0[i]);
    if (i < 512) { g_bh[i] = bh[i]; g_bo[i] = bo[i]; }
}

__global__ void xr_kernel(const float* __restrict__ x) {
    size_t i = ((size_t)blockIdx.x * blockDim.x + threadIdx.x) * 4;
    float4 v = *(const float4*)(x + i);
    v.x = rna_tf32(v.x); v.y = rna_tf32(v.y);
    v.z = rna_tf32(v.z); v.w = rna_tf32(v.w);
    *(float4*)(g_xr + i) = v;
}

// ------------- fp32 512^3 GEMM (matrix powers), 32x64 tile, grid(8,16) -------------
__global__ __launch_bounds__(256) void sq512(const float* __restrict__ A,
                                             const float* __restrict__ B,
                                             float* __restrict__ C,
                                             float* __restrict__ Ct) {
    __shared__ float As[16][36];
    __shared__ float Bs[16][64];
    const int tid = threadIdx.x;
    const int bm = blockIdx.y * 32, bn = blockIdx.x * 64;
    const int tx = tid & 15, ty = tid >> 4;
    const int ar = tid >> 3, ac2 = (tid & 7) * 2;
    const int br = tid >> 4, bc4 = (tid & 15) * 4;

    float acc[2][4] = {{0, 0, 0, 0}, {0, 0, 0, 0}};
    for (int k0 = 0; k0 < 512; k0 += 16) {
        float2 va = *(const float2*)(A + (size_t)(bm + ar) * 512 + k0 + ac2);
        float4 vb = *(const float4*)(B + (size_t)(k0 + br) * 512 + bn + bc4);
        __syncthreads();
        As[ac2 + 0][ar] = va.x;
        As[ac2 + 1][ar] = va.y;
        *(float4*)(&Bs[br][bc4]) = vb;
        __syncthreads();
#pragma unroll
        for (int kk = 0; kk < 16; kk++) {
            float a0 = As[kk][ty * 2 + 0], a1 = As[kk][ty * 2 + 1];
#pragma unroll
            for (int j = 0; j < 4; j++) {
                float b = Bs[kk][tx * 4 + j];
                acc[0][j] += a0 * b;
                acc[1][j] += a1 * b;
            }
        }
    }
#pragma unroll
    for (int i = 0; i < 2; i++) {
        int m = bm + ty * 2 + i;
        float4 v = {acc[i][0], acc[i][1], acc[i][2], acc[i][3]};
        *(float4*)(C + (size_t)m * 512 + bn + tx * 4) = v;
#pragma unroll
        for (int j = 0; j < 4; j++)
            Ct[(size_t)(bn + tx * 4 + j) * 512 + m] = rna_tf32(acc[i][j]);
    }
}

// ---------------- tf32 mma GEMM, 128x128 tile, 4-stage pipeline ----------------
// MODE 0: O = rna(A@Bt + bias)  K=512 (G1)
// MODE 1: O = sigmoid(A@Bt + bias), A=[xr | Hall-gather], K=1024 (G2)
// MODE 2: O = A@Bt + Add[addmap]  (rna if rnd)  K=512
// MODE 4: recovery, blk=bn>>9: Hall[4j+blk+1] = rna(Hall[4j]@W^(blk+1) + {preh(4j),R1,R2})
template <int MODE>
__global__ __launch_bounds__(256, 2) void mma_gemm(
    const float* __restrict__ A0, const float* __restrict__ A1, int amap, int aoff,
    const float* __restrict__ Add, int addmap, int addoff,
    float* __restrict__ O,
    const float* __restrict__ Bt, const float* __restrict__ bias, int rnd) {
    extern __shared__ float sm[];
    float* Asg = sm;            // 4 x 2560 floats
    float* Bsg = sm + 10240;

    const int tid = threadIdx.x;
    const int lane = tid & 31;
    const int wid = tid >> 5;
    const int wm = (wid >> 2) * 64;
    const int wn = (wid & 3) * 32;
    const int bm = blockIdx.y * 128;
    const int bn = blockIdx.x * 128;
    const int KD = (MODE == 1) ? 1024 : 512;
    const int NIT = KD / 16;
    const int ar1 = tid >> 2, ac = (tid & 3) * 4;

    const float* aP[2];
    const float* aH[2];
#pragma unroll
    for (int h = 0; h < 2; h++) {
        int gm = bm + ar1 + h * 64;
        if (MODE == 1) {
            aP[h] = A0 + (size_t)gm * 512 + ac;
            aH[h] = A1 + (size_t)((((gm & 255) << 8) | (gm >> 8))) * 512 + ac;
        } else {
            aP[h] = A0 + (size_t)rowmap(amap, aoff, gm) * 512 + ac;
        }
    }
    const float* bP = Bt + (size_t)(bn + ar1) * KD + ac;

    auto issue = [&](int it) {
        if (it < NIT) {
            const int k0 = it * 16;
            float* Ast = Asg + (it & 3) * 2560;
            float* Bst = Bsg + (it & 3) * 2560;
#pragma unroll
            for (int h = 0; h < 2; h++) {
                const float* src = (MODE == 1 && k0 >= 512) ? aH[h] + (k0 - 512) : aP[h] + k0;
                CP16(smem_u32(Ast + (ar1 + h * 64) * 20 + ac), src);
                CP16(smem_u32(Bst + (ar1 + h * 64) * 20 + ac), bP + (size_t)h * 64 * KD + k0);
            }
        }
        COMMIT();
    };

    const int rA = ((lane >> 3) & 1) * 8 + (lane & 7);
    const int cA = ((lane >> 4) & 1) * 4;
    const int rB = ((lane >> 4) & 1) * 8 + (lane & 7);
    const int cB = ((lane >> 3) & 1) * 4;
    uint32_t baseA[4], baseB[4];
#pragma unroll
    for (int s = 0; s < 4; s++) {
        baseA[s] = smem_u32(Asg + s * 2560 + (wm + rA) * 20 + cA);
        baseB[s] = smem_u32(Bsg + s * 2560 + (wn + rB) * 20 + cB);
    }

    float acc[4][4][4];
#pragma unroll
    for (int a = 0; a < 4; a++)
#pragma unroll
        for (int b = 0; b < 4; b++)
#pragma unroll
            for (int c = 0; c < 4; c++) acc[a][b][c] = 0.f;

    issue(0); issue(1); issue(2);
    for (int it = 0; it < NIT; it++) {
        WAIT2();
        __syncthreads();
        issue(it + 3);
        const int buf = it & 3;
#pragma unroll
        for (int kk = 0; kk < 2; kk++) {
            uint32_t af[4][4], bf[2][4];
#pragma unroll
            for (int mf = 0; mf < 4; mf++)
                LDSM4(af[mf][0], af[mf][1], af[mf][2], af[mf][3],
                      baseA[buf] + mf * 1280 + kk * 32);
#pragma unroll
            for (int p = 0; p < 2; p++)
                LDSM4(bf[p][0], bf[p][1], bf[p][2], bf[p][3],
                      baseB[buf] + p * 1280 + kk * 32);
#pragma unroll
            for (int mf = 0; mf < 4; mf++)
#pragma unroll
                for (int p = 0; p < 2; p++) {
                    mma8(acc[mf][2 * p + 0], af[mf], &bf[p][0]);
                    mma8(acc[mf][2 * p + 1], af[mf], &bf[p][2]);
                }
        }
    }

    const int blk = bn >> 9;
#pragma unroll
    for (int mf = 0; mf < 4; mf++)
#pragma unroll
        for (int nf = 0; nf < 4; nf++) {
            int col = bn + wn + nf * 8 + (lane & 3) * 2;
            int lc = col & 511;
#pragma unroll
            for (int h = 0; h < 2; h++) {
                int r = bm + wm + mf * 16 + (lane >> 2) + h * 8;
                float c0 = acc[mf][nf][h * 2 + 0];
                float c1 = acc[mf][nf][h * 2 + 1];
                float2 v;
                if (MODE == 0) {
                    v.x = rna_tf32(c0 + bias[col]);
                    v.y = rna_tf32(c1 + bias[col + 1]);
                    *(float2*)(O + (size_t)r * 512 + col) = v;
                } else if (MODE == 1) {
                    v.x = 1.f / (1.f + __expf(-(c0 + bias[col])));
                    v.y = 1.f / (1.f + __expf(-(c1 + bias[col + 1])));
                    *(float2*)(O + (size_t)r * 512 + col) = v;
                } else if (MODE == 2) {
                    const float* ap = Add + (size_t)rowmap(addmap, addoff, r) * 512 + col;
                    c0 += ap[0]; c1 += ap[1];
                    if (rnd) { v.x = rna_tf32(c0); v.y = rna_tf32(c1); }
                    else { v.x = c0; v.y = c1; }
                    *(float2*)(O + (size_t)r * 512 + col) = v;
                } else {  // MODE 4: fused recovery
                    int p0 = ((r >> 8) << 10) + (r & 255);
                    const float* ap;
                    if (blk == 0)      ap = g_preh + (size_t)p0 * 512 + lc;
                    else if (blk == 1) ap = g_Q1 + (size_t)r * 512 + lc;
                    else               ap = g_Q2 + (size_t)r * 512 + lc;
                    v.x = rna_tf32(c0 + ap[0]);
                    v.y = rna_tf32(c1 + ap[1]);
                    *(float2*)(g_Hall + (size_t)(p0 + ((blk + 1) << 8)) * 512 + lc) = v;
                }
            }
        }
}

// ---------------- persistent tensor-core scan, 4-stage pipeline ----------------
__device__ __forceinline__ void gbar(int target) {
    __syncthreads();
    if (threadIdx.x == 0) {
        __threadfence();
        int old = atomicAdd(&g_cnt, 1);
        if (old == 63) {
            g_cnt = 0;
            __threadfence();
            atomicExch(&g_phase, target);
        } else {
            while (atomicAdd(&g_phase, 0) < target) {}
        }
    }
    __syncthreads();
}

__global__ __launch_bounds__(256) void scan_kernel(const float* __restrict__ q4,
                                                   const float* __restrict__ q8,
                                                   float* __restrict__ outp) {
    extern __shared__ float sm[];
    float* Asg = sm;           // 4 x 640
    float* Bsg = sm + 2560;    // 4 x 2560
    const int tid = threadIdx.x;
    const int lane = tid & 31;
    const int wid = tid >> 5;
    const int wm = (wid >> 2) * 16;
    const int wn = (wid & 3) * 32;
    const int bn = blockIdx.x * 128;
    const int bm = blockIdx.y * 32;
    const int aar = tid >> 2, aac = (tid & 3) * 4;
    const int br = tid >> 2, bc = (tid & 3) * 4;
    const float* bP = g_WCt + (size_t)(bn + br) * 512 + bc;

    const int rA = ((lane >> 3) & 1) * 8 + (lane & 7);
    const int cA = ((lane >> 4) & 1) * 4;
    const int rB = ((lane >> 4) & 1) * 8 + (lane & 7);
    const int cB = ((lane >> 3) & 1) * 4;
    uint32_t baseA[4], baseB[4];
#pragma unroll
    for (int s = 0; s < 4; s++) {
        baseA[s] = smem_u32(Asg + s * 640 + (wm + rA) * 20 + cA);
        baseB[s] = smem_u32(Bsg + s * 2560 + (wn + rB) * 20 + cB);
    }

    for (int k = 0; k < 32; k++) {
        const float* hsrc = g_Hall + (size_t)(8 * k) * 131072;

        auto issue = [&](int it) {
            if (it < 32) {
                const int k0 = it * 16;
                float* Ast = Asg + (it & 3) * 640;
                float* Bst = Bsg + (it & 3) * 2560;
                if (tid < 128)
                    CP16(smem_u32(Ast + aar * 20 + aac),
                         hsrc + (size_t)(bm + aar) * 512 + k0 + aac);
#pragma unroll
                for (int h = 0; h < 2; h++)
                    CP16(smem_u32(Bst + (br + h * 64) * 20 + bc),
                         bP + (size_t)h * 64 * 512 + k0);
            }
            COMMIT();
        };

        float acc[4][4];
#pragma unroll
        for (int a = 0; a < 4; a++)
#pragma unroll
            for (int b = 0; b < 4; b++) acc[a][b] = 0.f;

        issue(0); issue(1); issue(2);
        for (int it = 0; it < 32; it++) {
            WAIT2();
            __syncthreads();
            issue(it + 3);
            const int buf = it & 3;
#pragma unroll
            for (int kk = 0; kk < 2; kk++) {
                uint32_t af[4], bf[2][4];
                LDSM4(af[0], af[1], af[2], af[3], baseA[buf] + kk * 32);
#pragma unroll
                for (int p = 0; p < 2; p++)
                    LDSM4(bf[p][0], bf[p][1], bf[p][2], bf[p][3],
                          baseB[buf] + p * 1280 + kk * 32);
#pragma unroll
                for (int p = 0; p < 2; p++) {
                    mma8(acc[2 * p + 0], af, &bf[p][0]);
                    mma8(acc[2 * p + 1], af, &bf[p][2]);
                }
            }
        }

#pragma unroll
        for (int nf = 0; nf < 4; nf++) {
            int col = bn + wn + nf * 8 + (lane & 3) * 2;
#pragma unroll
            for (int h = 0; h < 2; h++) {
                int r = bm + wm + (lane >> 2) + h * 8;
                float c0 = acc[nf][h * 2 + 0];
                float c1 = acc[nf][h * 2 + 1];
                size_t off = (size_t)r * 512;
                if (bn < 512) {
                    const float* p = q4 + (size_t)(2 * k) * 131072 + off + col;
                    float2 v = {rna_tf32(c0 + p[0]), rna_tf32(c1 + p[1])};
                    *(float2*)(g_Hall + (size_t)(8 * k + 4) * 131072 + off + col) = v;
                } else {
                    int c2 = col - 512;
                    const float* p = q8 + (size_t)k * 131072 + off + c2;
                    float f0 = c0 + p[0], f1 = c1 + p[1];
                    float2 v = {rna_tf32(f0), rna_tf32(f1)};
                    *(float2*)(g_Hall + (size_t)(8 * k + 8) * 131072 + off + c2) = v;
                    if (k == 31) {
                        float2 w = {f0, f1};
                        *(float2*)(outp + (size_t)33554432 + off + c2) = w;
                    }
                }
            }
        }
        gbar(k + 1);
    }
}

// ---------------- launch ----------------
extern "C" void kernel_launch(void* const* d_in, const int* in_sizes, int n_in,
                              void* d_out, int out_size) {
    const float* x  = (const float*)d_in[0];
    const float* h0 = (const float*)d_in[1];
    const float* Wh = (const float*)d_in[2];
    const float* bh = (const float*)d_in[3];
    const float* Wo = (const float*)d_in[4];
    const float* bo = (const float*)d_in[5];
    float* out = (float*)d_out;

    float *xr, *preh, *hall, *q0, *q1, *q2, *q3;
    float *whh, *w2, *w3, *w4, *w8, *w1t, *wrt, *wct, *wot, *bhp, *bop;
    cudaGetSymbolAddress((void**)&xr, g_xr);
    cudaGetSymbolAddress((void**)&preh, g_preh);
    cudaGetSymbolAddress((void**)&hall, g_Hall);
    cudaGetSymbolAddress((void**)&q0, g_Q0);
    cudaGetSymbolAddress((void**)&q1, g_Q1);
    cudaGetSymbolAddress((void**)&q2, g_Q2);
    cudaGetSymbolAddress((void**)&q3, g_Q3);
    cudaGetSymbolAddress((void**)&whh, g_Whh);
    cudaGetSymbolAddress((void**)&w2, g_W2);
    cudaGetSymbolAddress((void**)&w3, g_W3);
    cudaGetSymbolAddress((void**)&w4, g_W4);
    cudaGetSymbolAddress((void**)&w8, g_W8);
    cudaGetSymbolAddress((void**)&w1t, g_W1t);
    cudaGetSymbolAddress((void**)&wrt, g_WRt);
    cudaGetSymbolAddress((void**)&wct, g_WCt);
    cudaGetSymbolAddress((void**)&wot, g_Wot);
    cudaGetSymbolAddress((void**)&bhp, g_bh);
    cudaGetSymbolAddress((void**)&bop, g_bo);

    const int MMA_SMEM = 81920;
    const int SCAN_SMEM = 51200;

    static cudaStream_t s2 = nullptr, s3 = nullptr;
    static cudaEvent_t evRoot, evPrep, evXr, evSq;
    if (!s2) {
        cudaStreamCreateWithFlags(&s2, cudaStreamNonBlocking);
        cudaStreamCreateWithFlags(&s3, cudaStreamNonBlocking);
        cudaEventCreateWithFlags(&evRoot, cudaEventDisableTiming);
        cudaEventCreateWithFlags(&evPrep, cudaEventDisableTiming);
        cudaEventCreateWithFlags(&evXr, cudaEventDisableTiming);
        cudaEventCreateWithFlags(&evSq, cudaEventDisableTiming);
        cudaFuncSetAttribute(mma_gemm<0>, cudaFuncAttributeMaxDynamicSharedMemorySize, MMA_SMEM);
        cudaFuncSetAttribute(mma_gemm<1>, cudaFuncAttributeMaxDynamicSharedMemorySize, MMA_SMEM);
        cudaFuncSetAttribute(mma_gemm<2>, cudaFuncAttributeMaxDynamicSharedMemorySize, MMA_SMEM);
        cudaFuncSetAttribute(mma_gemm<4>, cudaFuncAttributeMaxDynamicSharedMemorySize, MMA_SMEM);
        cudaFuncSetAttribute(scan_kernel, cudaFuncAttributeMaxDynamicSharedMemorySize, SCAN_SMEM);
    }

    // fork: s3 does xr; s0 does prep; s2 does matrix powers after prep
    cudaEventRecord(evRoot, 0);
    cudaStreamWaitEvent(s3, evRoot, 0);
    xr_kernel<<<32768, 256, 0, s3>>>(x);
    cudaEventRecord(evXr, s3);

    prep_kernel<<<2048, 256>>>(Wh, bh, Wo, bo, h0);
    cudaEventRecord(evPrep, 0);
    cudaStreamWaitEvent(s2, evPrep, 0);
    sq512<<<dim3(8, 16), 256, 0, s2>>>(whh, whh, w2, wrt + 262144);   // W2, W2^T
    sq512<<<dim3(8, 16), 256, 0, s2>>>(w2, whh, w3, wrt + 524288);    // W3, W3^T
    sq512<<<dim3(8, 16), 256, 0, s2>>>(w2, w2, w4, wct);              // W4, W4^T
    sq512<<<dim3(8, 16), 256, 0, s2>>>(w4, w4, w8, wct + 262144);     // W8, W8^T
    cudaEventRecord(evSq, s2);

    // main chain on s0
    cudaStreamWaitEvent(0, evXr, 0);
    // G1: preh[t*256+b] = rna(xr[b][t] @ W_hx + b_h)
    mma_gemm<0><<<dim3(4, 512), 256, MMA_SMEM>>>(xr, nullptr, 1, 0, nullptr, 0, 0,
                                                 preh, w1t, bhp, 1);
    // Horner: R1 = preh(0)@W + preh(1); R2 = R1@W + preh(2); Q4 = R2@W + preh(3)
    mma_gemm<2><<<dim3(4, 128), 256, MMA_SMEM>>>(preh, nullptr, 2, 0, preh, 2, 1,
                                                 q1, wrt, nullptr, 1);
    mma_gemm<2><<<dim3(4, 128), 256, MMA_SMEM>>>(q1, nullptr, 0, 0, preh, 2, 2,
                                                 q2, wrt, nullptr, 1);
    mma_gemm<2><<<dim3(4, 128), 256, MMA_SMEM>>>(q2, nullptr, 0, 0, preh, 2, 3,
                                                 q0, wrt, nullptr, 1);
    // join matrix-power branch, then Q8 = Q4[2k]@W4 + Q4[2k+1] (fp32)
    cudaStreamWaitEvent(0, evSq, 0);
    mma_gemm<2><<<dim3(4, 64), 256, MMA_SMEM>>>(q0, nullptr, 3, 0, q0, 3, 1,
                                                q3, wct, nullptr, 0);
    // persistent scan (writes out tail at k=31)
    scan_kernel<<<dim3(8, 8), 256, SCAN_SMEM>>>(q0, q3, out);
    // fused recovery: Hall[4j+i] = rna(Hall[4j]@W^i + {preh(4j), R1, R2})
    mma_gemm<4><<<dim3(12, 128), 256, MMA_SMEM>>>(hall, nullptr, 2, 0, nullptr, 0, 0,
                                                  nullptr, wrt, nullptr, 1);
    // G2: out[b*256+t] = sigmoid([xr | Hall-gather] @ W_o + b_o)
    mma_gemm<1><<<dim3(4, 512), 256, MMA_SMEM>>>(xr, hall, 0, 0, nullptr, 0, 0,
                                                 out, wot, bop, 0);
}

// round 13
// speedup vs baseline: 1.1921x; 1.0819x over previous
#include <cuda_runtime.h>
#include <cstdint>

// ---------------- device-global scratch ----------------
__device__ float g_W1t[512 * 512];      // W_hx^T [n][k] tf32
__device__ float g_WRt[1536 * 512];     // [W^T ; W2^T ; W3^T] tf32 [n][k]
__device__ float g_WCt[1024 * 512];     // [W4^T ; W8^T] tf32 [n][k]
__device__ float g_Whh[512 * 512];      // W fp32
__device__ float g_W2[512 * 512];
__device__ float g_W3[512 * 512];
__device__ float g_W4[512 * 512];
__device__ float g_W8[512 * 512];
__device__ float g_Wot[512 * 1024];     // W_o^T [n][k] tf32
__device__ float g_bh[512];
__device__ float g_bo[512];
__device__ float g_xr[(size_t)65536 * 512];     // tf32-rounded x [b*256+t][k]
__device__ float g_preh[(size_t)65536 * 512];   // [t*256+b][n] tf32-rounded
__device__ float g_Hall[(size_t)257 * 131072];  // [t][b][n] tf32-rounded
__device__ float g_Q0[(size_t)16384 * 512];     // Q4
__device__ float g_Q1[(size_t)16384 * 512];     // R1
__device__ float g_Q2[(size_t)16384 * 512];     // R2
__device__ float g_Q3[(size_t)8192 * 512];      // Q8 (fp32)
__device__ int g_cnt, g_phase;

// ---------------- helpers ----------------
__device__ __forceinline__ uint32_t smem_u32(const void* p) {
    uint32_t a;
    asm("{ .reg .u64 t; cvta.to.shared.u64 t, %1; cvt.u32.u64 %0, t; }" : "=r"(a) : "l"(p));
    return a;
}
__device__ __forceinline__ float rna_tf32(float x) {
    uint32_t r; asm("cvt.rna.tf32.f32 %0, %1;" : "=r"(r) : "f"(x));
    return __uint_as_float(r);
}
// 0 id, 1 (b,t)swap, 2 chunk4 off, 3 chunk2 off
__device__ __forceinline__ int rowmap(int mode, int off, int m) {
    if (mode == 1) return ((m & 255) << 8) | (m >> 8);
    if (mode == 2) return ((m >> 8) << 10) + (off << 8) + (m & 255);
    if (mode == 3) return ((m >> 8) << 9) + (off << 8) + (m & 255);
    return m;
}
__device__ __forceinline__ void mma8(float* c, const uint32_t* a, const uint32_t* b) {
    asm volatile("mma.sync.aligned.m16n8k8.row.col.f32.tf32.tf32.f32 "
        "{%0,%1,%2,%3}, {%4,%5,%6,%7}, {%8,%9}, {%0,%1,%2,%3};"
        : "+f"(c[0]), "+f"(c[1]), "+f"(c[2]), "+f"(c[3])
        : "r"(a[0]), "r"(a[1]), "r"(a[2]), "r"(a[3]), "r"(b[0]), "r"(b[1]));
}
#define CP16(dst, src) asm volatile("cp.async.cg.shared.global [%0], [%1], 16;" :: "r"(dst), "l"(src))
#define LDSM4(r0, r1, r2, r3, addr)                                              \
    asm volatile("ldmatrix.sync.aligned.m8n8.x4.shared.b16 {%0,%1,%2,%3}, [%4];" \
        : "=r"(r0), "=r"(r1), "=r"(r2), "=r"(r3) : "r"(addr))
#define COMMIT() asm volatile("cp.async.commit_group;")
#define WAIT1()  asm volatile("cp.async.wait_group 1;")
#define WAIT2()  asm volatile("cp.async.wait_group 2;")

// ---------------- prep ----------------
__global__ void prep_kernel(const float* __restrict__ Wh, const float* __restrict__ bh,
                            const float* __restrict__ Wo, const float* __restrict__ bo,
                            const float* __restrict__ h0) {
    int i = blockIdx.x * blockDim.x + threadIdx.x;
    if (i == 0) { g_cnt = 0; g_phase = 0; }
    if (i < 524288) {                       // Wo [1024][512] -> Wot [n][k=1024]
        int k = i >> 9, n = i & 511;
        g_Wot[n * 1024 + k] = rna_tf32(Wo[i]);
    }
    if (i < 262144) {
        int k = i >> 9, n = i & 511;
        g_W1t[n * 512 + k] = rna_tf32(Wh[i]);
        float w = Wh[262144 + i];
        g_Whh[i] = w;
        g_WRt[n * 512 + k] = rna_tf32(w);   // W^T block 0 of WRt
    }
    if (i < 131072) g_Hall[i] = rna_tf32(h0[i]);
    if (i < 512) { g_bh[i] = bh[i]; g_bo[i] = bo[i]; }
}

__global__ void xr_kernel(const float* __restrict__ x) {
    size_t i = ((size_t)blockIdx.x * blockDim.x + threadIdx.x) * 4;
    float4 v = *(const float4*)(x + i);
    v.x = rna_tf32(v.x); v.y = rna_tf32(v.y);
    v.z = rna_tf32(v.z); v.w = rna_tf32(v.w);
    *(float4*)(g_xr + i) = v;
}

// ------------- fp32 512^3 GEMM (matrix powers), 32x64 tile, grid(8,16) -------------
__global__ __launch_bounds__(256) void sq512(const float* __restrict__ A,
                                             const float* __restrict__ B,
                                             float* __restrict__ C,
                                             float* __restrict__ Ct) {
    __shared__ float As[16][36];
    __shared__ float Bs[16][64];
    const int tid = threadIdx.x;
    const int bm = blockIdx.y * 32, bn = blockIdx.x * 64;
    const int tx = tid & 15, ty = tid >> 4;
    const int ar = tid >> 3, ac2 = (tid & 7) * 2;
    const int br = tid >> 4, bc4 = (tid & 15) * 4;

    float acc[2][4] = {{0, 0, 0, 0}, {0, 0, 0, 0}};
    for (int k0 = 0; k0 < 512; k0 += 16) {
        float2 va = *(const float2*)(A + (size_t)(bm + ar) * 512 + k0 + ac2);
        float4 vb = *(const float4*)(B + (size_t)(k0 + br) * 512 + bn + bc4);
        __syncthreads();
        As[ac2 + 0][ar] = va.x;
        As[ac2 + 1][ar] = va.y;
        *(float4*)(&Bs[br][bc4]) = vb;
        __syncthreads();
#pragma unroll
        for (int kk = 0; kk < 16; kk++) {
            float a0 = As[kk][ty * 2 + 0], a1 = As[kk][ty * 2 + 1];
#pragma unroll
            for (int j = 0; j < 4; j++) {
                float b = Bs[kk][tx * 4 + j];
                acc[0][j] += a0 * b;
                acc[1][j] += a1 * b;
            }
        }
    }
#pragma unroll
    for (int i = 0; i < 2; i++) {
        int m = bm + ty * 2 + i;
        float4 v = {acc[i][0], acc[i][1], acc[i][2], acc[i][3]};
        *(float4*)(C + (size_t)m * 512 + bn + tx * 4) = v;
#pragma unroll
        for (int j = 0; j < 4; j++)
            Ct[(size_t)(bn + tx * 4 + j) * 512 + m] = rna_tf32(acc[i][j]);
    }
}

// ---------------- tf32 mma GEMM, 128x128 tile, BK=32, 3-stage pipeline ----------------
// stage: A 128x32 (stride 36) + B 128x32 -> 36864 B; 3 stages = 110592 B
// MODE 0: O = rna(A@Bt + bias)  (G1)
// MODE 1: O = sigmoid(A@Bt + bias), A=[xr | Hall-gather], K=1024 (G2)
// MODE 2: O = A@Bt + Add[addmap]  (rna if rnd)
// MODE 4: recovery, blk=bn>>9: Hall[4j+blk+1] = rna(Hall[4j]@W^(blk+1) + {preh(4j),R1,R2})
template <int MODE>
__global__ __launch_bounds__(256, 2) void mma_gemm(
    const float* __restrict__ A0, const float* __restrict__ A1, int amap, int aoff,
    const float* __restrict__ Add, int addmap, int addoff,
    float* __restrict__ O,
    const float* __restrict__ Bt, const float* __restrict__ bias, int rnd) {
    extern __shared__ float sm[];
    float* Asg = sm;             // 3 x 4608 floats
    float* Bsg = sm + 13824;     // 3 x 4608 floats

    const int tid = threadIdx.x;
    const int lane = tid & 31;
    const int wid = tid >> 5;
    const int wm = (wid >> 2) * 64;
    const int wn = (wid & 3) * 32;
    const int bm = blockIdx.y * 128;
    const int bn = blockIdx.x * 128;
    const int KD = (MODE == 1) ? 1024 : 512;
    const int NIT = KD / 32;

    // loaders: 8 threads per 32-float row; 32 rows per round, 4 rounds
    const int lr = tid >> 3, lc = (tid & 7) * 4;

    const float* aP[4];
    const float* aH[4];
#pragma unroll
    for (int p = 0; p < 4; p++) {
        int gm = bm + lr + 32 * p;
        if (MODE == 1) {
            aP[p] = A0 + (size_t)gm * 512 + lc;
            aH[p] = A1 + (size_t)((((gm & 255) << 8) | (gm >> 8))) * 512 + lc;
        } else {
            aP[p] = A0 + (size_t)rowmap(amap, aoff, gm) * 512 + lc;
        }
    }
    const float* bP = Bt + (size_t)(bn + lr) * KD + lc;

    auto issue = [&](int it) {
        if (it < NIT) {
            const int k0 = it * 32;
            float* Ast = Asg + (it % 3) * 4608;
            float* Bst = Bsg + (it % 3) * 4608;
#pragma unroll
            for (int p = 0; p < 4; p++) {
                const float* src = (MODE == 1 && k0 >= 512) ? aH[p] + (k0 - 512) : aP[p] + k0;
                CP16(smem_u32(Ast + (lr + 32 * p) * 36 + lc), src);
                CP16(smem_u32(Bst + (lr + 32 * p) * 36 + lc), bP + (size_t)p * 32 * KD + k0);
            }
        }
        COMMIT();
    };

    const int rA = ((lane >> 3) & 1) * 8 + (lane & 7);
    const int cA = ((lane >> 4) & 1) * 4;
    const int rB = ((lane >> 4) & 1) * 8 + (lane & 7);
    const int cB = ((lane >> 3) & 1) * 4;
    uint32_t baseA[3], baseB[3];
#pragma unroll
    for (int s = 0; s < 3; s++) {
        baseA[s] = smem_u32(Asg + s * 4608 + (wm + rA) * 36 + cA);
        baseB[s] = smem_u32(Bsg + s * 4608 + (wn + rB) * 36 + cB);
    }

    float acc[4][4][4];
#pragma unroll
    for (int a = 0; a < 4; a++)
#pragma unroll
        for (int b = 0; b < 4; b++)
#pragma unroll
            for (int c = 0; c < 4; c++) acc[a][b][c] = 0.f;

    issue(0); issue(1);
    for (int it = 0; it < NIT; it++) {
        WAIT1();
        __syncthreads();
        issue(it + 2);
        const int buf = it % 3;
#pragma unroll
        for (int kk = 0; kk < 4; kk++) {
            uint32_t af[4][4], bf[2][4];
#pragma unroll
            for (int mf = 0; mf < 4; mf++)
                LDSM4(af[mf][0], af[mf][1], af[mf][2], af[mf][3],
                      baseA[buf] + mf * 2304 + kk * 32);
#pragma unroll
            for (int p = 0; p < 2; p++)
                LDSM4(bf[p][0], bf[p][1], bf[p][2], bf[p][3],
                      baseB[buf] + p * 2304 + kk * 32);
#pragma unroll
            for (int mf = 0; mf < 4; mf++)
#pragma unroll
                for (int p = 0; p < 2; p++) {
                    mma8(acc[mf][2 * p + 0], af[mf], &bf[p][0]);
                    mma8(acc[mf][2 * p + 1], af[mf], &bf[p][2]);
                }
        }
    }

    const int blk = bn >> 9;
#pragma unroll
    for (int mf = 0; mf < 4; mf++)
#pragma unroll
        for (int nf = 0; nf < 4; nf++) {
            int col = bn + wn + nf * 8 + (lane & 3) * 2;
            int lc2 = col & 511;
#pragma unroll
            for (int h = 0; h < 2; h++) {
                int r = bm + wm + mf * 16 + (lane >> 2) + h * 8;
                float c0 = acc[mf][nf][h * 2 + 0];
                float c1 = acc[mf][nf][h * 2 + 1];
                float2 v;
                if (MODE == 0) {
                    v.x = rna_tf32(c0 + bias[col]);
                    v.y = rna_tf32(c1 + bias[col + 1]);
                    *(float2*)(O + (size_t)r * 512 + col) = v;
                } else if (MODE == 1) {
                    v.x = 1.f / (1.f + __expf(-(c0 + bias[col])));
                    v.y = 1.f / (1.f + __expf(-(c1 + bias[col + 1])));
                    *(float2*)(O + (size_t)r * 512 + col) = v;
                } else if (MODE == 2) {
                    const float* ap = Add + (size_t)rowmap(addmap, addoff, r) * 512 + col;
                    c0 += ap[0]; c1 += ap[1];
                    if (rnd) { v.x = rna_tf32(c0); v.y = rna_tf32(c1); }
                    else { v.x = c0; v.y = c1; }
                    *(float2*)(O + (size_t)r * 512 + col) = v;
                } else {  // MODE 4: fused recovery
                    int p0 = ((r >> 8) << 10) + (r & 255);
                    const float* ap;
                    if (blk == 0)      ap = g_preh + (size_t)p0 * 512 + lc2;
                    else if (blk == 1) ap = g_Q1 + (size_t)r * 512 + lc2;
                    else               ap = g_Q2 + (size_t)r * 512 + lc2;
                    v.x = rna_tf32(c0 + ap[0]);
                    v.y = rna_tf32(c1 + ap[1]);
                    *(float2*)(g_Hall + (size_t)(p0 + ((blk + 1) << 8)) * 512 + lc2) = v;
                }
            }
        }
}

// ---------------- persistent tensor-core scan, 4-stage BK=16 pipeline ----------------
__device__ __forceinline__ void gbar(int target) {
    __syncthreads();
    if (threadIdx.x == 0) {
        __threadfence();
        int old = atomicAdd(&g_cnt, 1);
        if (old == 63) {
            g_cnt = 0;
            __threadfence();
            atomicExch(&g_phase, target);
        } else {
            while (atomicAdd(&g_phase, 0) < target) {}
        }
    }
    __syncthreads();
}

__global__ __launch_bounds__(256) void scan_kernel(const float* __restrict__ q4,
                                                   const float* __restrict__ q8,
                                                   float* __restrict__ outp) {
    extern __shared__ float sm[];
    float* Asg = sm;           // 4 x 640
    float* Bsg = sm + 2560;    // 4 x 2560
    const int tid = threadIdx.x;
    const int lane = tid & 31;
    const int wid = tid >> 5;
    const int wm = (wid >> 2) * 16;
    const int wn = (wid & 3) * 32;
    const int bn = blockIdx.x * 128;
    const int bm = blockIdx.y * 32;
    const int aar = tid >> 2, aac = (tid & 3) * 4;
    const int br = tid >> 2, bc = (tid & 3) * 4;
    const float* bP = g_WCt + (size_t)(bn + br) * 512 + bc;

    const int rA = ((lane >> 3) & 1) * 8 + (lane & 7);
    const int cA = ((lane >> 4) & 1) * 4;
    const int rB = ((lane >> 4) & 1) * 8 + (lane & 7);
    const int cB = ((lane >> 3) & 1) * 4;
    uint32_t baseA[4], baseB[4];
#pragma unroll
    for (int s = 0; s < 4; s++) {
        baseA[s] = smem_u32(Asg + s * 640 + (wm + rA) * 20 + cA);
        baseB[s] = smem_u32(Bsg + s * 2560 + (wn + rB) * 20 + cB);
    }

    for (int k = 0; k < 32; k++) {
        const float* hsrc = g_Hall + (size_t)(8 * k) * 131072;

        auto issue = [&](int it) {
            if (it < 32) {
                const int k0 = it * 16;
                float* Ast = Asg + (it & 3) * 640;
                float* Bst = Bsg + (it & 3) * 2560;
                if (tid < 128)
                    CP16(smem_u32(Ast + aar * 20 + aac),
                         hsrc + (size_t)(bm + aar) * 512 + k0 + aac);
#pragma unroll
                for (int h = 0; h < 2; h++)
                    CP16(smem_u32(Bst + (br + h * 64) * 20 + bc),
                         bP + (size_t)h * 64 * 512 + k0);
            }
            COMMIT();
        };

        float acc[4][4];
#pragma unroll
        for (int a = 0; a < 4; a++)
#pragma unroll
            for (int b = 0; b < 4; b++) acc[a][b] = 0.f;

        issue(0); issue(1); issue(2);
        for (int it = 0; it < 32; it++) {
            WAIT2();
            __syncthreads();
            issue(it + 3);
            const int buf = it & 3;
#pragma unroll
            for (int kk = 0; kk < 2; kk++) {
                uint32_t af[4], bf[2][4];
                LDSM4(af[0], af[1], af[2], af[3], baseA[buf] + kk * 32);
#pragma unroll
                for (int p = 0; p < 2; p++)
                    LDSM4(bf[p][0], bf[p][1], bf[p][2], bf[p][3],
                          baseB[buf] + p * 1280 + kk * 32);
#pragma unroll
                for (int p = 0; p < 2; p++) {
                    mma8(acc[2 * p + 0], af, &bf[p][0]);
                    mma8(acc[2 * p + 1], af, &bf[p][2]);
                }
            }
        }

#pragma unroll
        for (int nf = 0; nf < 4; nf++) {
            int col = bn + wn + nf * 8 + (lane & 3) * 2;
#pragma unroll
            for (int h = 0; h < 2; h++) {
                int r = bm + wm + (lane >> 2) + h * 8;
                float c0 = acc[nf][h * 2 + 0];
                float c1 = acc[nf][h * 2 + 1];
                size_t off = (size_t)r * 512;
                if (bn < 512) {
                    const float* p = q4 + (size_t)(2 * k) * 131072 + off + col;
                    float2 v = {rna_tf32(c0 + p[0]), rna_tf32(c1 + p[1])};
                    *(float2*)(g_Hall + (size_t)(8 * k + 4) * 131072 + off + col) = v;
                } else {
                    int c2 = col - 512;
                    const float* p = q8 + (size_t)k * 131072 + off + c2;
                    float f0 = c0 + p[0], f1 = c1 + p[1];
                    float2 v = {rna_tf32(f0), rna_tf32(f1)};
                    *(float2*)(g_Hall + (size_t)(8 * k + 8) * 131072 + off + c2) = v;
                    if (k == 31) {
                        float2 w = {f0, f1};
                        *(float2*)(outp + (size_t)33554432 + off + c2) = w;
                    }
                }
            }
        }
        gbar(k + 1);
    }
}

// ---------------- launch ----------------
extern "C" void kernel_launch(void* const* d_in, const int* in_sizes, int n_in,
                              void* d_out, int out_size) {
    const float* x  = (const float*)d_in[0];
    const float* h0 = (const float*)d_in[1];
    const float* Wh = (const float*)d_in[2];
    const float* bh = (const float*)d_in[3];
    const float* Wo = (const float*)d_in[4];
    const float* bo = (const float*)d_in[5];
    float* out = (float*)d_out;

    float *xr, *preh, *hall, *q0, *q1, *q2, *q3;
    float *whh, *w2, *w3, *w4, *w8, *w1t, *wrt, *wct, *wot, *bhp, *bop;
    cudaGetSymbolAddress((void**)&xr, g_xr);
    cudaGetSymbolAddress((void**)&preh, g_preh);
    cudaGetSymbolAddress((void**)&hall, g_Hall);
    cudaGetSymbolAddress((void**)&q0, g_Q0);
    cudaGetSymbolAddress((void**)&q1, g_Q1);
    cudaGetSymbolAddress((void**)&q2, g_Q2);
    cudaGetSymbolAddress((void**)&q3, g_Q3);
    cudaGetSymbolAddress((void**)&whh, g_Whh);
    cudaGetSymbolAddress((void**)&w2, g_W2);
    cudaGetSymbolAddress((void**)&w3, g_W3);
    cudaGetSymbolAddress((void**)&w4, g_W4);
    cudaGetSymbolAddress((void**)&w8, g_W8);
    cudaGetSymbolAddress((void**)&w1t, g_W1t);
    cudaGetSymbolAddress((void**)&wrt, g_WRt);
    cudaGetSymbolAddress((void**)&wct, g_WCt);
    cudaGetSymbolAddress((void**)&wot, g_Wot);
    cudaGetSymbolAddress((void**)&bhp, g_bh);
    cudaGetSymbolAddress((void**)&bop, g_bo);

    const int MMA_SMEM = 110592;
    const int SCAN_SMEM = 51200;

    static cudaStream_t s2 = nullptr, s3 = nullptr;
    static cudaEvent_t evRoot, evPrep, evXr, evSq4, evSq8;
    if (!s2) {
        cudaStreamCreateWithFlags(&s2, cudaStreamNonBlocking);
        cudaStreamCreateWithFlags(&s3, cudaStreamNonBlocking);
        cudaEventCreateWithFlags(&evRoot, cudaEventDisableTiming);
        cudaEventCreateWithFlags(&evPrep, cudaEventDisableTiming);
        cudaEventCreateWithFlags(&evXr, cudaEventDisableTiming);
        cudaEventCreateWithFlags(&evSq4, cudaEventDisableTiming);
        cudaEventCreateWithFlags(&evSq8, cudaEventDisableTiming);
        cudaFuncSetAttribute(mma_gemm<0>, cudaFuncAttributeMaxDynamicSharedMemorySize, MMA_SMEM);
        cudaFuncSetAttribute(mma_gemm<1>, cudaFuncAttributeMaxDynamicSharedMemorySize, MMA_SMEM);
        cudaFuncSetAttribute(mma_gemm<2>, cudaFuncAttributeMaxDynamicSharedMemorySize, MMA_SMEM);
        cudaFuncSetAttribute(mma_gemm<4>, cudaFuncAttributeMaxDynamicSharedMemorySize, MMA_SMEM);
        cudaFuncSetAttribute(scan_kernel, cudaFuncAttributeMaxDynamicSharedMemorySize, SCAN_SMEM);
    }

    // fork: s3 xr(1); s0 prep(2); s2 powers W2,W3,W4 (3-5); s0 G1 (6, ncu target)
    cudaEventRecord(evRoot, 0);
    cudaStreamWaitEvent(s3, evRoot, 0);
    xr_kernel<<<32768, 256, 0, s3>>>(x);
    cudaEventRecord(evXr, s3);

    prep_kernel<<<2048, 256>>>(Wh, bh, Wo, bo, h0);
    cudaEventRecord(evPrep, 0);
    cudaStreamWaitEvent(s2, evPrep, 0);
    sq512<<<dim3(8, 16), 256, 0, s2>>>(whh, whh, w2, wrt + 262144);   // W2, W2^T
    sq512<<<dim3(8, 16), 256, 0, s2>>>(w2, whh, w3, wrt + 524288);    // W3, W3^T
    sq512<<<dim3(8, 16), 256, 0, s2>>>(w2, w2, w4, wct);              // W4, W4^T
    cudaEventRecord(evSq4, s2);

    // main chain on s0
    cudaStreamWaitEvent(0, evXr, 0);
    // G1 (launch #6): preh[t*256+b] = rna(xr[b][t] @ W_hx + b_h)
    mma_gemm<0><<<dim3(4, 512), 256, MMA_SMEM>>>(xr, nullptr, 1, 0, nullptr, 0, 0,
                                                 preh, w1t, bhp, 1);

    // last power on s2 (launch #7)
    sq512<<<dim3(8, 16), 256, 0, s2>>>(w4, w4, w8, wct + 262144);     // W8, W8^T
    cudaEventRecord(evSq8, s2);

    // Horner: R1 = preh(0)@W + preh(1); R2 = R1@W + preh(2); Q4 = R2@W + preh(3)
    mma_gemm<2><<<dim3(4, 128), 256, MMA_SMEM>>>(preh, nullptr, 2, 0, preh, 2, 1,
                                                 q1, wrt, nullptr, 1);
    mma_gemm<2><<<dim3(4, 128), 256, MMA_SMEM>>>(q1, nullptr, 0, 0, preh, 2, 2,
                                                 q2, wrt, nullptr, 1);
    mma_gemm<2><<<dim3(4, 128), 256, MMA_SMEM>>>(q2, nullptr, 0, 0, preh, 2, 3,
                                                 q0, wrt, nullptr, 1);
    // Q8 = Q4[2k]@W4 + Q4[2k+1] (fp32) — needs W4
    cudaStreamWaitEvent(0, evSq4, 0);
    mma_gemm<2><<<dim3(4, 64), 256, MMA_SMEM>>>(q0, nullptr, 3, 0, q0, 3, 1,
                                                q3, wct, nullptr, 0);
    // persistent scan — needs W8
    cudaStreamWaitEvent(0, evSq8, 0);
    scan_kernel<<<dim3(8, 8), 256, SCAN_SMEM>>>(q0, q3, out);
    // fused recovery: Hall[4j+i] = rna(Hall[4j]@W^i + {preh(4j), R1, R2})
    mma_gemm<4><<<dim3(12, 128), 256, MMA_SMEM>>>(hall, nullptr, 2, 0, nullptr, 0, 0,
                                                  nullptr, wrt, nullptr, 1);
    // G2: out[b*256+t] = sigmoid([xr | Hall-gather] @ W_o + b_o)
    mma_gemm<1><<<dim3(4, 512), 256, MMA_SMEM>>>(xr, hall, 0, 0, nullptr, 0, 0,
                                                 out, wot, bop, 0);
}

// round 14
// speedup vs baseline: 1.2689x; 1.0644x over previous
#include <cuda_runtime.h>
#include <cstdint>

// ---------------- device-global scratch ----------------
__device__ float g_W1t[512 * 512];      // W_hx^T [n][k] tf32
__device__ float g_WRt[1536 * 512];     // [W^T ; W2^T ; W3^T] tf32 [n][k]
__device__ float g_WCt[2048 * 512];     // [W4^T ; W8^T ; W12^T ; W16^T] tf32 [n][k]
__device__ float g_Whh[512 * 512];      // W fp32
__device__ float g_W2[512 * 512];
__device__ float g_W3[512 * 512];
__device__ float g_W4[512 * 512];
__device__ float g_W8[512 * 512];
__device__ float g_W12[512 * 512];
__device__ float g_W16[512 * 512];
__device__ float g_Wot[512 * 1024];     // W_o^T [n][k] tf32
__device__ float g_bh[512];
__device__ float g_bo[512];
__device__ float g_xr[(size_t)65536 * 512];     // tf32-rounded x [b*256+t][k]
__device__ float g_preh[(size_t)65536 * 512];   // [t*256+b][n] tf32-rounded
__device__ float g_Hall[(size_t)257 * 131072];  // [t][b][n] tf32-rounded
__device__ float g_Q0[(size_t)16384 * 512];     // Q4 (rounded)
__device__ float g_Q1[(size_t)16384 * 512];     // R1
__device__ float g_Q2[(size_t)16384 * 512];     // R2
__device__ float g_Q3[(size_t)8192 * 512];      // Q8 (fp32)
__device__ float g_Q12[(size_t)4096 * 512];     // Q12 (fp32)
__device__ float g_Q16[(size_t)4096 * 512];     // Q16 (fp32)
__device__ int g_cnt, g_phase;

// ---------------- helpers ----------------
__device__ __forceinline__ uint32_t smem_u32(const void* p) {
    uint32_t a;
    asm("{ .reg .u64 t; cvta.to.shared.u64 t, %1; cvt.u32.u64 %0, t; }" : "=r"(a) : "l"(p));
    return a;
}
__device__ __forceinline__ float rna_tf32(float x) {
    uint32_t r; asm("cvt.rna.tf32.f32 %0, %1;" : "=r"(r) : "f"(x));
    return __uint_as_float(r);
}
// 0 id, 1 (b,t)swap, 2 chunk4 off, 3 chunk2 off
__device__ __forceinline__ int rowmap(int mode, int off, int m) {
    if (mode == 1) return ((m & 255) << 8) | (m >> 8);
    if (mode == 2) return ((m >> 8) << 10) + (off << 8) + (m & 255);
    if (mode == 3) return ((m >> 8) << 9) + (off << 8) + (m & 255);
    return m;
}
__device__ __forceinline__ void mma8(float* c, const uint32_t* a, const uint32_t* b) {
    asm volatile("mma.sync.aligned.m16n8k8.row.col.f32.tf32.tf32.f32 "
        "{%0,%1,%2,%3}, {%4,%5,%6,%7}, {%8,%9}, {%0,%1,%2,%3};"
        : "+f"(c[0]), "+f"(c[1]), "+f"(c[2]), "+f"(c[3])
        : "r"(a[0]), "r"(a[1]), "r"(a[2]), "r"(a[3]), "r"(b[0]), "r"(b[1]));
}
#define CP16(dst, src) asm volatile("cp.async.cg.shared.global [%0], [%1], 16;" :: "r"(dst), "l"(src))
#define LDSM4(r0, r1, r2, r3, addr)                                              \
    asm volatile("ldmatrix.sync.aligned.m8n8.x4.shared.b16 {%0,%1,%2,%3}, [%4];" \
        : "=r"(r0), "=r"(r1), "=r"(r2), "=r"(r3) : "r"(addr))
#define COMMIT() asm volatile("cp.async.commit_group;")
#define WAIT1()  asm volatile("cp.async.wait_group 1;")
#define WAIT2()  asm volatile("cp.async.wait_group 2;")

// ---------------- prep ----------------
__global__ void prep_kernel(const float* __restrict__ Wh, const float* __restrict__ bh,
                            const float* __restrict__ Wo, const float* __restrict__ bo,
                            const float* __restrict__ h0) {
    int i = blockIdx.x * blockDim.x + threadIdx.x;
    if (i == 0) { g_cnt = 0; g_phase = 0; }
    if (i < 524288) {                       // Wo [1024][512] -> Wot [n][k=1024]
        int k = i >> 9, n = i & 511;
        g_Wot[n * 1024 + k] = rna_tf32(Wo[i]);
    }
    if (i < 262144) {
        int k = i >> 9, n = i & 511;
        g_W1t[n * 512 + k] = rna_tf32(Wh[i]);
        float w = Wh[262144 + i];
        g_Whh[i] = w;
        g_WRt[n * 512 + k] = rna_tf32(w);   // W^T block 0 of WRt
    }
    if (i < 131072) g_Hall[i] = rna_tf32(h0[i]);
    if (i < 512) { g_bh[i] = bh[i]; g_bo[i] = bo[i]; }
}

__global__ void xr_kernel(const float* __restrict__ x) {
    size_t i = ((size_t)blockIdx.x * blockDim.x + threadIdx.x) * 4;
    float4 v = *(const float4*)(x + i);
    v.x = rna_tf32(v.x); v.y = rna_tf32(v.y);
    v.z = rna_tf32(v.z); v.w = rna_tf32(v.w);
    *(float4*)(g_xr + i) = v;
}

// ------------- fp32 512^3 GEMM (matrix powers), 32x64 tile, grid(8,16) -------------
__global__ __launch_bounds__(256) void sq512(const float* __restrict__ A,
                                             const float* __restrict__ B,
                                             float* __restrict__ C,
                                             float* __restrict__ Ct) {
    __shared__ float As[16][36];
    __shared__ float Bs[16][64];
    const int tid = threadIdx.x;
    const int bm = blockIdx.y * 32, bn = blockIdx.x * 64;
    const int tx = tid & 15, ty = tid >> 4;
    const int ar = tid >> 3, ac2 = (tid & 7) * 2;
    const int br = tid >> 4, bc4 = (tid & 15) * 4;

    float acc[2][4] = {{0, 0, 0, 0}, {0, 0, 0, 0}};
    for (int k0 = 0; k0 < 512; k0 += 16) {
        float2 va = *(const float2*)(A + (size_t)(bm + ar) * 512 + k0 + ac2);
        float4 vb = *(const float4*)(B + (size_t)(k0 + br) * 512 + bn + bc4);
        __syncthreads();
        As[ac2 + 0][ar] = va.x;
        As[ac2 + 1][ar] = va.y;
        *(float4*)(&Bs[br][bc4]) = vb;
        __syncthreads();
#pragma unroll
        for (int kk = 0; kk < 16; kk++) {
            float a0 = As[kk][ty * 2 + 0], a1 = As[kk][ty * 2 + 1];
#pragma unroll
            for (int j = 0; j < 4; j++) {
                float b = Bs[kk][tx * 4 + j];
                acc[0][j] += a0 * b;
                acc[1][j] += a1 * b;
            }
        }
    }
#pragma unroll
    for (int i = 0; i < 2; i++) {
        int m = bm + ty * 2 + i;
        float4 v = {acc[i][0], acc[i][1], acc[i][2], acc[i][3]};
        *(float4*)(C + (size_t)m * 512 + bn + tx * 4) = v;
#pragma unroll
        for (int j = 0; j < 4; j++)
            Ct[(size_t)(bn + tx * 4 + j) * 512 + m] = rna_tf32(acc[i][j]);
    }
}

// ---------------- tf32 mma GEMM, 128x128 tile, BK=32, 3-stage pipeline ----------------
// MODE 0: O = rna(A@Bt + bias)  (G1)
// MODE 1: O = sigmoid(A@Bt + bias), A=[xr | Hall-gather], K=1024 (G2)
// MODE 2: O = A@Bt + Add[addmap]  (rna if rnd)
// MODE 4: recovery, blk=bn>>9: Hall[4j+blk+1] = rna(Hall[4j]@W^(blk+1) + {preh(4j),R1,R2})
// MODE 5: QC, A=Q8[2k]: blk 0: Q12 = acc + Q4[4k+2]; blk 1: Q16 = acc + Q8[2k+1] (fp32)
template <int MODE>
__global__ __launch_bounds__(256, 2) void mma_gemm(
    const float* __restrict__ A0, const float* __restrict__ A1, int amap, int aoff,
    const float* __restrict__ Add, int addmap, int addoff,
    float* __restrict__ O,
    const float* __restrict__ Bt, const float* __restrict__ bias, int rnd) {
    extern __shared__ float sm[];
    float* Asg = sm;             // 3 x 4608 floats
    float* Bsg = sm + 13824;     // 3 x 4608 floats

    const int tid = threadIdx.x;
    const int lane = tid & 31;
    const int wid = tid >> 5;
    const int wm = (wid >> 2) * 64;
    const int wn = (wid & 3) * 32;
    const int bm = blockIdx.y * 128;
    const int bn = blockIdx.x * 128;
    const int KD = (MODE == 1) ? 1024 : 512;
    const int NIT = KD / 32;

    const int lr = tid >> 3, lc = (tid & 7) * 4;

    const float* aP[4];
    const float* aH[4];
#pragma unroll
    for (int p = 0; p < 4; p++) {
        int gm = bm + lr + 32 * p;
        if (MODE == 1) {
            aP[p] = A0 + (size_t)gm * 512 + lc;
            aH[p] = A1 + (size_t)((((gm & 255) << 8) | (gm >> 8))) * 512 + lc;
        } else {
            aP[p] = A0 + (size_t)rowmap(amap, aoff, gm) * 512 + lc;
        }
    }
    const float* bP = Bt + (size_t)(bn + lr) * KD + lc;

    auto issue = [&](int it) {
        if (it < NIT) {
            const int k0 = it * 32;
            float* Ast = Asg + (it % 3) * 4608;
            float* Bst = Bsg + (it % 3) * 4608;
#pragma unroll
            for (int p = 0; p < 4; p++) {
                const float* src = (MODE == 1 && k0 >= 512) ? aH[p] + (k0 - 512) : aP[p] + k0;
                CP16(smem_u32(Ast + (lr + 32 * p) * 36 + lc), src);
                CP16(smem_u32(Bst + (lr + 32 * p) * 36 + lc), bP + (size_t)p * 32 * KD + k0);
            }
        }
        COMMIT();
    };

    const int rA = ((lane >> 3) & 1) * 8 + (lane & 7);
    const int cA = ((lane >> 4) & 1) * 4;
    const int rB = ((lane >> 4) & 1) * 8 + (lane & 7);
    const int cB = ((lane >> 3) & 1) * 4;
    uint32_t baseA[3], baseB[3];
#pragma unroll
    for (int s = 0; s < 3; s++) {
        baseA[s] = smem_u32(Asg + s * 4608 + (wm + rA) * 36 + cA);
        baseB[s] = smem_u32(Bsg + s * 4608 + (wn + rB) * 36 + cB);
    }

    float acc[4][4][4];
#pragma unroll
    for (int a = 0; a < 4; a++)
#pragma unroll
        for (int b = 0; b < 4; b++)
#pragma unroll
            for (int c = 0; c < 4; c++) acc[a][b][c] = 0.f;

    issue(0); issue(1);
    for (int it = 0; it < NIT; it++) {
        WAIT1();
        __syncthreads();
        issue(it + 2);
        const int buf = it % 3;
#pragma unroll
        for (int kk = 0; kk < 4; kk++) {
            uint32_t af[4][4], bf[2][4];
#pragma unroll
            for (int mf = 0; mf < 4; mf++)
                LDSM4(af[mf][0], af[mf][1], af[mf][2], af[mf][3],
                      baseA[buf] + mf * 2304 + kk * 32);
#pragma unroll
            for (int p = 0; p < 2; p++)
                LDSM4(bf[p][0], bf[p][1], bf[p][2], bf[p][3],
                      baseB[buf] + p * 2304 + kk * 32);
#pragma unroll
            for (int mf = 0; mf < 4; mf++)
#pragma unroll
                for (int p = 0; p < 2; p++) {
                    mma8(acc[mf][2 * p + 0], af[mf], &bf[p][0]);
                    mma8(acc[mf][2 * p + 1], af[mf], &bf[p][2]);
                }
        }
    }

    const int blk = bn >> 9;
#pragma unroll
    for (int mf = 0; mf < 4; mf++)
#pragma unroll
        for (int nf = 0; nf < 4; nf++) {
            int col = bn + wn + nf * 8 + (lane & 3) * 2;
            int lc2 = col & 511;
#pragma unroll
            for (int h = 0; h < 2; h++) {
                int r = bm + wm + mf * 16 + (lane >> 2) + h * 8;
                float c0 = acc[mf][nf][h * 2 + 0];
                float c1 = acc[mf][nf][h * 2 + 1];
                float2 v;
                if (MODE == 0) {
                    v.x = rna_tf32(c0 + bias[col]);
                    v.y = rna_tf32(c1 + bias[col + 1]);
                    *(float2*)(O + (size_t)r * 512 + col) = v;
                } else if (MODE == 1) {
                    v.x = 1.f / (1.f + __expf(-(c0 + bias[col])));
                    v.y = 1.f / (1.f + __expf(-(c1 + bias[col + 1])));
                    *(float2*)(O + (size_t)r * 512 + col) = v;
                } else if (MODE == 2) {
                    const float* ap = Add + (size_t)rowmap(addmap, addoff, r) * 512 + col;
                    c0 += ap[0]; c1 += ap[1];
                    if (rnd) { v.x = rna_tf32(c0); v.y = rna_tf32(c1); }
                    else { v.x = c0; v.y = c1; }
                    *(float2*)(O + (size_t)r * 512 + col) = v;
                } else if (MODE == 4) {  // fused recovery
                    int p0 = ((r >> 8) << 10) + (r & 255);
                    const float* ap;
                    if (blk == 0)      ap = g_preh + (size_t)p0 * 512 + lc2;
                    else if (blk == 1) ap = g_Q1 + (size_t)r * 512 + lc2;
                    else               ap = g_Q2 + (size_t)r * 512 + lc2;
                    v.x = rna_tf32(c0 + ap[0]);
                    v.y = rna_tf32(c1 + ap[1]);
                    *(float2*)(g_Hall + (size_t)(p0 + ((blk + 1) << 8)) * 512 + lc2) = v;
                } else {  // MODE 5: Q12 / Q16 (fp32 outputs)
                    if (blk == 0) {
                        const float* ap = g_Q0 + (size_t)rowmap(2, 2, r) * 512 + lc2;
                        v.x = c0 + ap[0];
                        v.y = c1 + ap[1];
                        *(float2*)(g_Q12 + (size_t)r * 512 + lc2) = v;
                    } else {
                        const float* ap = g_Q3 + (size_t)rowmap(3, 1, r) * 512 + lc2;
                        v.x = c0 + ap[0];
                        v.y = c1 + ap[1];
                        *(float2*)(g_Q16 + (size_t)r * 512 + lc2) = v;
                    }
                }
            }
        }
}

// ---------------- persistent tensor-core scan: C=16, 16 supersteps ----------------
// superstep k: C[256x2048] = Hall[16k] @ [W4t;W8t;W12t;W16t]
//   blk b=0..3: Hall[16k+4(b+1)] = rna(C_b + {Q4[4k], Q8[2k], Q12[k], Q16[k]})
//   blk3, k==15: also write fp32 h_final to out tail
__device__ __forceinline__ void gbar(int target) {
    __syncthreads();
    if (threadIdx.x == 0) {
        __threadfence();
        int old = atomicAdd(&g_cnt, 1);
        if (old == 127) {
            g_cnt = 0;
            __threadfence();
            atomicExch(&g_phase, target);
        } else {
            while (atomicAdd(&g_phase, 0) < target) {}
        }
    }
    __syncthreads();
}

__global__ __launch_bounds__(256) void scan_kernel(const float* __restrict__ q4,
                                                   const float* __restrict__ q8,
                                                   float* __restrict__ outp) {
    extern __shared__ float sm[];
    float* Asg = sm;           // 4 x 640
    float* Bsg = sm + 2560;    // 4 x 2560
    const int tid = threadIdx.x;
    const int lane = tid & 31;
    const int wid = tid >> 5;
    const int wm = (wid >> 2) * 16;
    const int wn = (wid & 3) * 32;
    const int bn = blockIdx.x * 128;     // over N=2048
    const int bm = blockIdx.y * 32;      // over M=256
    const int blk = bn >> 9;             // 0..3 -> W4/W8/W12/W16
    const int aar = tid >> 2, aac = (tid & 3) * 4;
    const int br = tid >> 2, bc = (tid & 3) * 4;
    const float* bP = g_WCt + (size_t)(bn + br) * 512 + bc;

    const int rA = ((lane >> 3) & 1) * 8 + (lane & 7);
    const int cA = ((lane >> 4) & 1) * 4;
    const int rB = ((lane >> 4) & 1) * 8 + (lane & 7);
    const int cB = ((lane >> 3) & 1) * 4;
    uint32_t baseA[4], baseB[4];
#pragma unroll
    for (int s = 0; s < 4; s++) {
        baseA[s] = smem_u32(Asg + s * 640 + (wm + rA) * 20 + cA);
        baseB[s] = smem_u32(Bsg + s * 2560 + (wn + rB) * 20 + cB);
    }

    for (int k = 0; k < 16; k++) {
        const float* hsrc = g_Hall + (size_t)(16 * k) * 131072;

        auto issue = [&](int it) {
            if (it < 32) {
                const int k0 = it * 16;
                float* Ast = Asg + (it & 3) * 640;
                float* Bst = Bsg + (it & 3) * 2560;
                if (tid < 128)
                    CP16(smem_u32(Ast + aar * 20 + aac),
                         hsrc + (size_t)(bm + aar) * 512 + k0 + aac);
#pragma unroll
                for (int h = 0; h < 2; h++)
                    CP16(smem_u32(Bst + (br + h * 64) * 20 + bc),
                         bP + (size_t)h * 64 * 512 + k0);
            }
            COMMIT();
        };

        float acc[4][4];
#pragma unroll
        for (int a = 0; a < 4; a++)
#pragma unroll
            for (int b = 0; b < 4; b++) acc[a][b] = 0.f;

        issue(0); issue(1); issue(2);
        for (int it = 0; it < 32; it++) {
            WAIT2();
            __syncthreads();
            issue(it + 3);
            const int buf = it & 3;
#pragma unroll
            for (int kk = 0; kk < 2; kk++) {
                uint32_t af[4], bf[2][4];
                LDSM4(af[0], af[1], af[2], af[3], baseA[buf] + kk * 32);
#pragma unroll
                for (int p = 0; p < 2; p++)
                    LDSM4(bf[p][0], bf[p][1], bf[p][2], bf[p][3],
                          baseB[buf] + p * 1280 + kk * 32);
#pragma unroll
                for (int p = 0; p < 2; p++) {
                    mma8(acc[2 * p + 0], af, &bf[p][0]);
                    mma8(acc[2 * p + 1], af, &bf[p][2]);
                }
            }
        }

        // per-blk Add source row base
        const float* qsrc;
        int rowbase;
        if (blk == 0)      { qsrc = q4;    rowbase = (4 * k) << 8; }
        else if (blk == 1) { qsrc = q8;    rowbase = (2 * k) << 8; }
        else if (blk == 2) { qsrc = g_Q12; rowbase = k << 8; }
        else               { qsrc = g_Q16; rowbase = k << 8; }
        float* hdst = g_Hall + (size_t)(16 * k + 4 * (blk + 1)) * 131072;

#pragma unroll
        for (int nf = 0; nf < 4; nf++) {
            int col = bn + wn + nf * 8 + (lane & 3) * 2;
            int lc2 = col & 511;
#pragma unroll
            for (int h = 0; h < 2; h++) {
                int r = bm + wm + (lane >> 2) + h * 8;
                float c0 = acc[nf][h * 2 + 0];
                float c1 = acc[nf][h * 2 + 1];
                const float* p = qsrc + (size_t)(rowbase + r) * 512 + lc2;
                float f0 = c0 + p[0], f1 = c1 + p[1];
                float2 v = {rna_tf32(f0), rna_tf32(f1)};
                *(float2*)(hdst + (size_t)r * 512 + lc2) = v;
                if (blk == 3 && k == 15) {
                    float2 w = {f0, f1};
                    *(float2*)(outp + (size_t)33554432 + (size_t)r * 512 + lc2) = w;
                }
            }
        }
        gbar(k + 1);
    }
}

// ---------------- launch ----------------
extern "C" void kernel_launch(void* const* d_in, const int* in_sizes, int n_in,
                              void* d_out, int out_size) {
    const float* x  = (const float*)d_in[0];
    const float* h0 = (const float*)d_in[1];
    const float* Wh = (const float*)d_in[2];
    const float* bh = (const float*)d_in[3];
    const float* Wo = (const float*)d_in[4];
    const float* bo = (const float*)d_in[5];
    float* out = (float*)d_out;

    float *xr, *preh, *hall, *q0, *q1, *q2, *q3;
    float *whh, *w2, *w3, *w4, *w8, *w12, *w16, *w1t, *wrt, *wct, *wot, *bhp, *bop;
    cudaGetSymbolAddress((void**)&xr, g_xr);
    cudaGetSymbolAddress((void**)&preh, g_preh);
    cudaGetSymbolAddress((void**)&hall, g_Hall);
    cudaGetSymbolAddress((void**)&q0, g_Q0);
    cudaGetSymbolAddress((void**)&q1, g_Q1);
    cudaGetSymbolAddress((void**)&q2, g_Q2);
    cudaGetSymbolAddress((void**)&q3, g_Q3);
    cudaGetSymbolAddress((void**)&whh, g_Whh);
    cudaGetSymbolAddress((void**)&w2, g_W2);
    cudaGetSymbolAddress((void**)&w3, g_W3);
    cudaGetSymbolAddress((void**)&w4, g_W4);
    cudaGetSymbolAddress((void**)&w8, g_W8);
    cudaGetSymbolAddress((void**)&w12, g_W12);
    cudaGetSymbolAddress((void**)&w16, g_W16);
    cudaGetSymbolAddress((void**)&w1t, g_W1t);
    cudaGetSymbolAddress((void**)&wrt, g_WRt);
    cudaGetSymbolAddress((void**)&wct, g_WCt);
    cudaGetSymbolAddress((void**)&wot, g_Wot);
    cudaGetSymbolAddress((void**)&bhp, g_bh);
    cudaGetSymbolAddress((void**)&bop, g_bo);

    const int MMA_SMEM = 110592;
    const int SCAN_SMEM = 51200;

    static cudaStream_t s2 = nullptr, s3 = nullptr;
    static cudaEvent_t evRoot, evPrep, evXr, evSq4, evSq8, evSqAll;
    if (!s2) {
        cudaStreamCreateWithFlags(&s2, cudaStreamNonBlocking);
        cudaStreamCreateWithFlags(&s3, cudaStreamNonBlocking);
        cudaEventCreateWithFlags(&evRoot, cudaEventDisableTiming);
        cudaEventCreateWithFlags(&evPrep, cudaEventDisableTiming);
        cudaEventCreateWithFlags(&evXr, cudaEventDisableTiming);
        cudaEventCreateWithFlags(&evSq4, cudaEventDisableTiming);
        cudaEventCreateWithFlags(&evSq8, cudaEventDisableTiming);
        cudaEventCreateWithFlags(&evSqAll, cudaEventDisableTiming);
        cudaFuncSetAttribute(mma_gemm<0>, cudaFuncAttributeMaxDynamicSharedMemorySize, MMA_SMEM);
        cudaFuncSetAttribute(mma_gemm<1>, cudaFuncAttributeMaxDynamicSharedMemorySize, MMA_SMEM);
        cudaFuncSetAttribute(mma_gemm<2>, cudaFuncAttributeMaxDynamicSharedMemorySize, MMA_SMEM);
        cudaFuncSetAttribute(mma_gemm<4>, cudaFuncAttributeMaxDynamicSharedMemorySize, MMA_SMEM);
        cudaFuncSetAttribute(mma_gemm<5>, cudaFuncAttributeMaxDynamicSharedMemorySize, MMA_SMEM);
        cudaFuncSetAttribute(scan_kernel, cudaFuncAttributeMaxDynamicSharedMemorySize, SCAN_SMEM);
    }

    // fork: s3 xr; s0 prep; s2 matrix powers
    cudaEventRecord(evRoot, 0);
    cudaStreamWaitEvent(s3, evRoot, 0);
    xr_kernel<<<32768, 256, 0, s3>>>(x);
    cudaEventRecord(evXr, s3);

    prep_kernel<<<2048, 256>>>(Wh, bh, Wo, bo, h0);
    cudaEventRecord(evPrep, 0);
    cudaStreamWaitEvent(s2, evPrep, 0);
    sq512<<<dim3(8, 16), 256, 0, s2>>>(whh, whh, w2, wrt + 262144);   // W2, W2^T
    sq512<<<dim3(8, 16), 256, 0, s2>>>(w2, whh, w3, wrt + 524288);    // W3, W3^T
    sq512<<<dim3(8, 16), 256, 0, s2>>>(w2, w2, w4, wct);              // W4, W4^T
    cudaEventRecord(evSq4, s2);
    sq512<<<dim3(8, 16), 256, 0, s2>>>(w4, w4, w8, wct + 262144);     // W8, W8^T
    cudaEventRecord(evSq8, s2);
    sq512<<<dim3(8, 16), 256, 0, s2>>>(w4, w8, w12, wct + 524288);    // W12, W12^T
    sq512<<<dim3(8, 16), 256, 0, s2>>>(w8, w8, w16, wct + 786432);    // W16, W16^T
    cudaEventRecord(evSqAll, s2);

    // main chain on s0
    cudaStreamWaitEvent(0, evXr, 0);
    // G1: preh[t*256+b] = rna(xr[b][t] @ W_hx + b_h)
    mma_gemm<0><<<dim3(4, 512), 256, MMA_SMEM>>>(xr, nullptr, 1, 0, nullptr, 0, 0,
                                                 preh, w1t, bhp, 1);
    // Horner: R1 = preh(0)@W + preh(1); R2 = R1@W + preh(2); Q4 = R2@W + preh(3)
    mma_gemm<2><<<dim3(4, 128), 256, MMA_SMEM>>>(preh, nullptr, 2, 0, preh, 2, 1,
                                                 q1, wrt, nullptr, 1);
    mma_gemm<2><<<dim3(4, 128), 256, MMA_SMEM>>>(q1, nullptr, 0, 0, preh, 2, 2,
                                                 q2, wrt, nullptr, 1);
    mma_gemm<2><<<dim3(4, 128), 256, MMA_SMEM>>>(q2, nullptr, 0, 0, preh, 2, 3,
                                                 q0, wrt, nullptr, 1);
    // Q8 = Q4[2k]@W4 + Q4[2k+1] (fp32) — needs W4
    cudaStreamWaitEvent(0, evSq4, 0);
    mma_gemm<2><<<dim3(4, 64), 256, MMA_SMEM>>>(q0, nullptr, 3, 0, q0, 3, 1,
                                                q3, wct, nullptr, 0);
    // QC: Q12 = Q8[2k]@W4 + Q4[4k+2]; Q16 = Q8[2k]@W8 + Q8[2k+1] — needs W4,W8
    cudaStreamWaitEvent(0, evSq8, 0);
    mma_gemm<5><<<dim3(8, 32), 256, MMA_SMEM>>>(q3, nullptr, 3, 0, nullptr, 0, 0,
                                                nullptr, wct, nullptr, 0);
    // persistent scan (16 supersteps) — needs W12,W16
    cudaStreamWaitEvent(0, evSqAll, 0);
    scan_kernel<<<dim3(16, 8), 256, SCAN_SMEM>>>(q0, q3, out);
    // fused recovery: Hall[4j+i] = rna(Hall[4j]@W^i + {preh(4j), R1, R2})
    mma_gemm<4><<<dim3(12, 128), 256, MMA_SMEM>>>(hall, nullptr, 2, 0, nullptr, 0, 0,
                                                  nullptr, wrt, nullptr, 1);
    // G2: out[b*256+t] = sigmoid([xr | Hall-gather] @ W_o + b_o)
    mma_gemm<1><<<dim3(4, 512), 256, MMA_SMEM>>>(xr, hall, 0, 0, nullptr, 0, 0,
                                                 out, wot, bop, 0);
}

// round 15
// speedup vs baseline: 1.2711x; 1.0017x over previous
#include <cuda_runtime.h>
#include <cstdint>

// ---------------- device-global scratch ----------------
__device__ float g_W1t[512 * 512];      // W_hx^T [n][k] tf32
__device__ float g_WRt[1536 * 512];     // [W^T ; W2^T ; W3^T] tf32 [n][k]
__device__ float g_WCt[2048 * 512];     // [W4^T ; W8^T ; W12^T ; W16^T] tf32 [n][k]
__device__ float g_Whh[512 * 512];      // W fp32
__device__ float g_W2[512 * 512];
__device__ float g_W3[512 * 512];
__device__ float g_W4[512 * 512];
__device__ float g_W8[512 * 512];
__device__ float g_W12[512 * 512];
__device__ float g_W16[512 * 512];
__device__ float g_Wot[512 * 1024];     // W_o^T [n][k] tf32
__device__ float g_bh[512];
__device__ float g_bo[512];
__device__ float g_xr[(size_t)65536 * 512];     // tf32-rounded x [b*256+t][k]
__device__ float g_preh[(size_t)65536 * 512];   // [t*256+b][n] tf32-rounded
__device__ float g_Hall[(size_t)257 * 131072];  // [t][b][n] tf32-rounded
__device__ float g_Q0[(size_t)16384 * 512];     // Q4 (rounded)
__device__ float g_Q1[(size_t)16384 * 512];     // R1
__device__ float g_Q2[(size_t)16384 * 512];     // R2
__device__ float g_Q3[(size_t)8192 * 512];      // Q8 (fp32)
__device__ float g_Q12[(size_t)4096 * 512];     // Q12 (fp32)
__device__ float g_Q16[(size_t)4096 * 512];     // Q16 (fp32)
__device__ int g_cnt, g_phase;

// ---------------- helpers ----------------
__device__ __forceinline__ uint32_t smem_u32(const void* p) {
    uint32_t a;
    asm("{ .reg .u64 t; cvta.to.shared.u64 t, %1; cvt.u32.u64 %0, t; }" : "=r"(a) : "l"(p));
    return a;
}
__device__ __forceinline__ float rna_tf32(float x) {
    uint32_t r; asm("cvt.rna.tf32.f32 %0, %1;" : "=r"(r) : "f"(x));
    return __uint_as_float(r);
}
// 0 id, 1 (b,t)swap, 2 chunk4 off, 3 chunk2 off
__device__ __forceinline__ int rowmap(int mode, int off, int m) {
    if (mode == 1) return ((m & 255) << 8) | (m >> 8);
    if (mode == 2) return ((m >> 8) << 10) + (off << 8) + (m & 255);
    if (mode == 3) return ((m >> 8) << 9) + (off << 8) + (m & 255);
    return m;
}
__device__ __forceinline__ void mma8(float* c, const uint32_t* a, const uint32_t* b) {
    asm volatile("mma.sync.aligned.m16n8k8.row.col.f32.tf32.tf32.f32 "
        "{%0,%1,%2,%3}, {%4,%5,%6,%7}, {%8,%9}, {%0,%1,%2,%3};"
        : "+f"(c[0]), "+f"(c[1]), "+f"(c[2]), "+f"(c[3])
        : "r"(a[0]), "r"(a[1]), "r"(a[2]), "r"(a[3]), "r"(b[0]), "r"(b[1]));
}
#define CP16(dst, src) asm volatile("cp.async.cg.shared.global [%0], [%1], 16;" :: "r"(dst), "l"(src))
#define LDSM4(r0, r1, r2, r3, addr)                                              \
    asm volatile("ldmatrix.sync.aligned.m8n8.x4.shared.b16 {%0,%1,%2,%3}, [%4];" \
        : "=r"(r0), "=r"(r1), "=r"(r2), "=r"(r3) : "r"(addr))
#define COMMIT() asm volatile("cp.async.commit_group;")
#define WAIT1()  asm volatile("cp.async.wait_group 1;")
#define WAIT2()  asm volatile("cp.async.wait_group 2;")

// ---------------- prep ----------------
__global__ void prep_kernel(const float* __restrict__ Wh, const float* __restrict__ bh,
                            const float* __restrict__ Wo, const float* __restrict__ bo,
                            const float* __restrict__ h0) {
    int i = blockIdx.x * blockDim.x + threadIdx.x;
    if (i == 0) { g_cnt = 0; g_phase = 0; }
    if (i < 524288) {                       // Wo [1024][512] -> Wot [n][k=1024]
        int k = i >> 9, n = i & 511;
        g_Wot[n * 1024 + k] = rna_tf32(Wo[i]);
    }
    if (i < 262144) {
        int k = i >> 9, n = i & 511;
        g_W1t[n * 512 + k] = rna_tf32(Wh[i]);
        float w = Wh[262144 + i];
        g_Whh[i] = w;
        g_WRt[n * 512 + k] = rna_tf32(w);   // W^T block 0 of WRt
    }
    if (i < 131072) g_Hall[i] = rna_tf32(h0[i]);
    if (i < 512) { g_bh[i] = bh[i]; g_bo[i] = bo[i]; }
}

__global__ void xr_kernel(const float* __restrict__ x) {
    size_t i = ((size_t)blockIdx.x * blockDim.x + threadIdx.x) * 4;
    float4 v = *(const float4*)(x + i);
    v.x = rna_tf32(v.x); v.y = rna_tf32(v.y);
    v.z = rna_tf32(v.z); v.w = rna_tf32(v.w);
    *(float4*)(g_xr + i) = v;
}

// ------------- fp32 512^3 GEMM (matrix powers), 32x64 tile, grid(8,16) -------------
__global__ __launch_bounds__(256) void sq512(const float* __restrict__ A,
                                             const float* __restrict__ B,
                                             float* __restrict__ C,
                                             float* __restrict__ Ct) {
    __shared__ float As[16][36];
    __shared__ float Bs[16][64];
    const int tid = threadIdx.x;
    const int bm = blockIdx.y * 32, bn = blockIdx.x * 64;
    const int tx = tid & 15, ty = tid >> 4;
    const int ar = tid >> 3, ac2 = (tid & 7) * 2;
    const int br = tid >> 4, bc4 = (tid & 15) * 4;

    float acc[2][4] = {{0, 0, 0, 0}, {0, 0, 0, 0}};
    for (int k0 = 0; k0 < 512; k0 += 16) {
        float2 va = *(const float2*)(A + (size_t)(bm + ar) * 512 + k0 + ac2);
        float4 vb = *(const float4*)(B + (size_t)(k0 + br) * 512 + bn + bc4);
        __syncthreads();
        As[ac2 + 0][ar] = va.x;
        As[ac2 + 1][ar] = va.y;
        *(float4*)(&Bs[br][bc4]) = vb;
        __syncthreads();
#pragma unroll
        for (int kk = 0; kk < 16; kk++) {
            float a0 = As[kk][ty * 2 + 0], a1 = As[kk][ty * 2 + 1];
#pragma unroll
            for (int j = 0; j < 4; j++) {
                float b = Bs[kk][tx * 4 + j];
                acc[0][j] += a0 * b;
                acc[1][j] += a1 * b;
            }
        }
    }
#pragma unroll
    for (int i = 0; i < 2; i++) {
        int m = bm + ty * 2 + i;
        float4 v = {acc[i][0], acc[i][1], acc[i][2], acc[i][3]};
        *(float4*)(C + (size_t)m * 512 + bn + tx * 4) = v;
#pragma unroll
        for (int j = 0; j < 4; j++)
            Ct[(size_t)(bn + tx * 4 + j) * 512 + m] = rna_tf32(acc[i][j]);
    }
}

// ---------------- tf32 mma GEMM, 128x128 tile, BK=32, 3-stage pipeline ----------------
// MODE 0: O = rna(A@Bt + bias)  (G1)
// MODE 1: O = sigmoid(A@Bt + bias), A=[xr | Hall-gather], K=1024 (G2)
// MODE 2: O = A@Bt + Add[addmap]  (rna if rnd)
// MODE 4: recovery, blk=bn>>9: Hall[4j+blk+1] = rna(Hall[4j]@W^(blk+1) + {preh(4j),R1,R2})
// MODE 5: QC, A=Q8[2k]: blk 0: Q12 = acc + Q4[4k+2]; blk 1: Q16 = acc + Q8[2k+1] (fp32)
template <int MODE>
__global__ __launch_bounds__(256, 2) void mma_gemm(
    const float* __restrict__ A0, const float* __restrict__ A1, int amap, int aoff,
    const float* __restrict__ Add, int addmap, int addoff,
    float* __restrict__ O,
    const float* __restrict__ Bt, const float* __restrict__ bias, int rnd) {
    extern __shared__ float sm[];
    float* Asg = sm;             // 3 x 4608 floats
    float* Bsg = sm + 13824;     // 3 x 4608 floats

    const int tid = threadIdx.x;
    const int lane = tid & 31;
    const int wid = tid >> 5;
    const int wm = (wid >> 2) * 64;
    const int wn = (wid & 3) * 32;
    const int bm = blockIdx.y * 128;
    const int bn = blockIdx.x * 128;
    const int KD = (MODE == 1) ? 1024 : 512;
    const int NIT = KD / 32;

    const int lr = tid >> 3, lc = (tid & 7) * 4;

    const float* aP[4];
    const float* aH[4];
#pragma unroll
    for (int p = 0; p < 4; p++) {
        int gm = bm + lr + 32 * p;
        if (MODE == 1) {
            aP[p] = A0 + (size_t)gm * 512 + lc;
            aH[p] = A1 + (size_t)((((gm & 255) << 8) | (gm >> 8))) * 512 + lc;
        } else {
            aP[p] = A0 + (size_t)rowmap(amap, aoff, gm) * 512 + lc;
        }
    }
    const float* bP = Bt + (size_t)(bn + lr) * KD + lc;

    auto issue = [&](int it) {
        if (it < NIT) {
            const int k0 = it * 32;
            float* Ast = Asg + (it % 3) * 4608;
            float* Bst = Bsg + (it % 3) * 4608;
#pragma unroll
            for (int p = 0; p < 4; p++) {
                const float* src = (MODE == 1 && k0 >= 512) ? aH[p] + (k0 - 512) : aP[p] + k0;
                CP16(smem_u32(Ast + (lr + 32 * p) * 36 + lc), src);
                CP16(smem_u32(Bst + (lr + 32 * p) * 36 + lc), bP + (size_t)p * 32 * KD + k0);
            }
        }
        COMMIT();
    };

    const int rA = ((lane >> 3) & 1) * 8 + (lane & 7);
    const int cA = ((lane >> 4) & 1) * 4;
    const int rB = ((lane >> 4) & 1) * 8 + (lane & 7);
    const int cB = ((lane >> 3) & 1) * 4;
    uint32_t baseA[3], baseB[3];
#pragma unroll
    for (int s = 0; s < 3; s++) {
        baseA[s] = smem_u32(Asg + s * 4608 + (wm + rA) * 36 + cA);
        baseB[s] = smem_u32(Bsg + s * 4608 + (wn + rB) * 36 + cB);
    }

    float acc[4][4][4];
#pragma unroll
    for (int a = 0; a < 4; a++)
#pragma unroll
        for (int b = 0; b < 4; b++)
#pragma unroll
            for (int c = 0; c < 4; c++) acc[a][b][c] = 0.f;

    issue(0); issue(1);
    for (int it = 0; it < NIT; it++) {
        WAIT1();
        __syncthreads();
        issue(it + 2);
        const int buf = it % 3;
#pragma unroll
        for (int kk = 0; kk < 4; kk++) {
            uint32_t af[4][4], bf[2][4];
#pragma unroll
            for (int mf = 0; mf < 4; mf++)
                LDSM4(af[mf][0], af[mf][1], af[mf][2], af[mf][3],
                      baseA[buf] + mf * 2304 + kk * 32);
#pragma unroll
            for (int p = 0; p < 2; p++)
                LDSM4(bf[p][0], bf[p][1], bf[p][2], bf[p][3],
                      baseB[buf] + p * 2304 + kk * 32);
#pragma unroll
            for (int mf = 0; mf < 4; mf++)
#pragma unroll
                for (int p = 0; p < 2; p++) {
                    mma8(acc[mf][2 * p + 0], af[mf], &bf[p][0]);
                    mma8(acc[mf][2 * p + 1], af[mf], &bf[p][2]);
                }
        }
    }

    const int blk = bn >> 9;
#pragma unroll
    for (int mf = 0; mf < 4; mf++)
#pragma unroll
        for (int nf = 0; nf < 4; nf++) {
            int col = bn + wn + nf * 8 + (lane & 3) * 2;
            int lc2 = col & 511;
#pragma unroll
            for (int h = 0; h < 2; h++) {
                int r = bm + wm + mf * 16 + (lane >> 2) + h * 8;
                float c0 = acc[mf][nf][h * 2 + 0];
                float c1 = acc[mf][nf][h * 2 + 1];
                float2 v;
                if (MODE == 0) {
                    v.x = rna_tf32(c0 + bias[col]);
                    v.y = rna_tf32(c1 + bias[col + 1]);
                    *(float2*)(O + (size_t)r * 512 + col) = v;
                } else if (MODE == 1) {
                    v.x = 1.f / (1.f + __expf(-(c0 + bias[col])));
                    v.y = 1.f / (1.f + __expf(-(c1 + bias[col + 1])));
                    *(float2*)(O + (size_t)r * 512 + col) = v;
                } else if (MODE == 2) {
                    const float* ap = Add + (size_t)rowmap(addmap, addoff, r) * 512 + col;
                    c0 += ap[0]; c1 += ap[1];
                    if (rnd) { v.x = rna_tf32(c0); v.y = rna_tf32(c1); }
                    else { v.x = c0; v.y = c1; }
                    *(float2*)(O + (size_t)r * 512 + col) = v;
                } else if (MODE == 4) {  // fused recovery
                    int p0 = ((r >> 8) << 10) + (r & 255);
                    const float* ap;
                    if (blk == 0)      ap = g_preh + (size_t)p0 * 512 + lc2;
                    else if (blk == 1) ap = g_Q1 + (size_t)r * 512 + lc2;
                    else               ap = g_Q2 + (size_t)r * 512 + lc2;
                    v.x = rna_tf32(c0 + ap[0]);
                    v.y = rna_tf32(c1 + ap[1]);
                    *(float2*)(g_Hall + (size_t)(p0 + ((blk + 1) << 8)) * 512 + lc2) = v;
                } else {  // MODE 5: Q12 / Q16 (fp32 outputs)
                    if (blk == 0) {
                        const float* ap = g_Q0 + (size_t)rowmap(2, 2, r) * 512 + lc2;
                        v.x = c0 + ap[0];
                        v.y = c1 + ap[1];
                        *(float2*)(g_Q12 + (size_t)r * 512 + lc2) = v;
                    } else {
                        const float* ap = g_Q3 + (size_t)rowmap(3, 1, r) * 512 + lc2;
                        v.x = c0 + ap[0];
                        v.y = c1 + ap[1];
                        *(float2*)(g_Q16 + (size_t)r * 512 + lc2) = v;
                    }
                }
            }
        }
}

// ---------------- persistent tensor-core scan: C=16, 16 supersteps ----------------
// superstep k: C[256x2048] = Hall[16k] @ [W4t;W8t;W12t;W16t]
//   blk b=0..3: Hall[16k+4(b+1)] = rna(C_b + {Q4[4k], Q8[2k], Q12[k], Q16[k]})
//   blk3, k==15: also write fp32 h_final to out tail
__device__ __forceinline__ void gbar(int target) {
    __syncthreads();
    if (threadIdx.x == 0) {
        __threadfence();
        int old = atomicAdd(&g_cnt, 1);
        if (old == 127) {
            g_cnt = 0;
            __threadfence();
            atomicExch(&g_phase, target);
        } else {
            while (atomicAdd(&g_phase, 0) < target) {}
        }
    }
    __syncthreads();
}

__global__ __launch_bounds__(256) void scan_kernel(const float* __restrict__ q4,
                                                   const float* __restrict__ q8,
                                                   float* __restrict__ outp) {
    extern __shared__ float sm[];
    float* Asg = sm;           // 4 x 640
    float* Bsg = sm + 2560;    // 4 x 2560
    const int tid = threadIdx.x;
    const int lane = tid & 31;
    const int wid = tid >> 5;
    const int wm = (wid >> 2) * 16;
    const int wn = (wid & 3) * 32;
    const int bn = blockIdx.x * 128;     // over N=2048
    const int bm = blockIdx.y * 32;      // over M=256
    const int blk = bn >> 9;             // 0..3 -> W4/W8/W12/W16
    const int aar = tid >> 2, aac = (tid & 3) * 4;
    const int br = tid >> 2, bc = (tid & 3) * 4;
    const float* bP = g_WCt + (size_t)(bn + br) * 512 + bc;

    const int rA = ((lane >> 3) & 1) * 8 + (lane & 7);
    const int cA = ((lane >> 4) & 1) * 4;
    const int rB = ((lane >> 4) & 1) * 8 + (lane & 7);
    const int cB = ((lane >> 3) & 1) * 4;
    uint32_t baseA[4], baseB[4];
#pragma unroll
    for (int s = 0; s < 4; s++) {
        baseA[s] = smem_u32(Asg + s * 640 + (wm + rA) * 20 + cA);
        baseB[s] = smem_u32(Bsg + s * 2560 + (wn + rB) * 20 + cB);
    }

    for (int k = 0; k < 16; k++) {
        const float* hsrc = g_Hall + (size_t)(16 * k) * 131072;

        auto issue = [&](int it) {
            if (it < 32) {
                const int k0 = it * 16;
                float* Ast = Asg + (it & 3) * 640;
                float* Bst = Bsg + (it & 3) * 2560;
                if (tid < 128)
                    CP16(smem_u32(Ast + aar * 20 + aac),
                         hsrc + (size_t)(bm + aar) * 512 + k0 + aac);
#pragma unroll
                for (int h = 0; h < 2; h++)
                    CP16(smem_u32(Bst + (br + h * 64) * 20 + bc),
                         bP + (size_t)h * 64 * 512 + k0);
            }
            COMMIT();
        };

        float acc[4][4];
#pragma unroll
        for (int a = 0; a < 4; a++)
#pragma unroll
            for (int b = 0; b < 4; b++) acc[a][b] = 0.f;

        issue(0); issue(1); issue(2);
        for (int it = 0; it < 32; it++) {
            WAIT2();
            __syncthreads();
            issue(it + 3);
            const int buf = it & 3;
#pragma unroll
            for (int kk = 0; kk < 2; kk++) {
                uint32_t af[4], bf[2][4];
                LDSM4(af[0], af[1], af[2], af[3], baseA[buf] + kk * 32);
#pragma unroll
                for (int p = 0; p < 2; p++)
                    LDSM4(bf[p][0], bf[p][1], bf[p][2], bf[p][3],
                          baseB[buf] + p * 1280 + kk * 32);
#pragma unroll
                for (int p = 0; p < 2; p++) {
                    mma8(acc[2 * p + 0], af, &bf[p][0]);
                    mma8(acc[2 * p + 1], af, &bf[p][2]);
                }
            }
        }

        // per-blk Add source row base
        const float* qsrc;
        int rowbase;
        if (blk == 0)      { qsrc = q4;    rowbase = (4 * k) << 8; }
        else if (blk == 1) { qsrc = q8;    rowbase = (2 * k) << 8; }
        else if (blk == 2) { qsrc = g_Q12; rowbase = k << 8; }
        else               { qsrc = g_Q16; rowbase = k << 8; }
        float* hdst = g_Hall + (size_t)(16 * k + 4 * (blk + 1)) * 131072;

#pragma unroll
        for (int nf = 0; nf < 4; nf++) {
            int col = bn + wn + nf * 8 + (lane & 3) * 2;
            int lc2 = col & 511;
#pragma unroll
            for (int h = 0; h < 2; h++) {
                int r = bm + wm + (lane >> 2) + h * 8;
                float c0 = acc[nf][h * 2 + 0];
                float c1 = acc[nf][h * 2 + 1];
                const float* p = qsrc + (size_t)(rowbase + r) * 512 + lc2;
                float f0 = c0 + p[0], f1 = c1 + p[1];
                float2 v = {rna_tf32(f0), rna_tf32(f1)};
                *(float2*)(hdst + (size_t)r * 512 + lc2) = v;
                if (blk == 3 && k == 15) {
                    float2 w = {f0, f1};
                    *(float2*)(outp + (size_t)33554432 + (size_t)r * 512 + lc2) = w;
                }
            }
        }
        gbar(k + 1);
    }
}

// ---------------- launch ----------------
extern "C" void kernel_launch(void* const* d_in, const int* in_sizes, int n_in,
                              void* d_out, int out_size) {
    const float* x  = (const float*)d_in[0];
    const float* h0 = (const float*)d_in[1];
    const float* Wh = (const float*)d_in[2];
    const float* bh = (const float*)d_in[3];
    const float* Wo = (const float*)d_in[4];
    const float* bo = (const float*)d_in[5];
    float* out = (float*)d_out;

    float *xr, *preh, *hall, *q0, *q1, *q2, *q3;
    float *whh, *w2, *w3, *w4, *w8, *w12, *w16, *w1t, *wrt, *wct, *wot, *bhp, *bop;
    cudaGetSymbolAddress((void**)&xr, g_xr);
    cudaGetSymbolAddress((void**)&preh, g_preh);
    cudaGetSymbolAddress((void**)&hall, g_Hall);
    cudaGetSymbolAddress((void**)&q0, g_Q0);
    cudaGetSymbolAddress((void**)&q1, g_Q1);
    cudaGetSymbolAddress((void**)&q2, g_Q2);
    cudaGetSymbolAddress((void**)&q3, g_Q3);
    cudaGetSymbolAddress((void**)&whh, g_Whh);
    cudaGetSymbolAddress((void**)&w2, g_W2);
    cudaGetSymbolAddress((void**)&w3, g_W3);
    cudaGetSymbolAddress((void**)&w4, g_W4);
    cudaGetSymbolAddress((void**)&w8, g_W8);
    cudaGetSymbolAddress((void**)&w12, g_W12);
    cudaGetSymbolAddress((void**)&w16, g_W16);
    cudaGetSymbolAddress((void**)&w1t, g_W1t);
    cudaGetSymbolAddress((void**)&wrt, g_WRt);
    cudaGetSymbolAddress((void**)&wct, g_WCt);
    cudaGetSymbolAddress((void**)&wot, g_Wot);
    cudaGetSymbolAddress((void**)&bhp, g_bh);
    cudaGetSymbolAddress((void**)&bop, g_bo);

    const int MMA_SMEM = 110592;
    const int SCAN_SMEM = 51200;

    static cudaStream_t s2 = nullptr, s3 = nullptr;
    static cudaEvent_t evRoot, evPrep, evXr, evSq4, evSq8, evSqAll;
    if (!s2) {
        cudaStreamCreateWithFlags(&s2, cudaStreamNonBlocking);
        cudaStreamCreateWithFlags(&s3, cudaStreamNonBlocking);
        cudaEventCreateWithFlags(&evRoot, cudaEventDisableTiming);
        cudaEventCreateWithFlags(&evPrep, cudaEventDisableTiming);
        cudaEventCreateWithFlags(&evXr, cudaEventDisableTiming);
        cudaEventCreateWithFlags(&evSq4, cudaEventDisableTiming);
        cudaEventCreateWithFlags(&evSq8, cudaEventDisableTiming);
        cudaEventCreateWithFlags(&evSqAll, cudaEventDisableTiming);
        cudaFuncSetAttribute(mma_gemm<0>, cudaFuncAttributeMaxDynamicSharedMemorySize, MMA_SMEM);
        cudaFuncSetAttribute(mma_gemm<1>, cudaFuncAttributeMaxDynamicSharedMemorySize, MMA_SMEM);
        cudaFuncSetAttribute(mma_gemm<2>, cudaFuncAttributeMaxDynamicSharedMemorySize, MMA_SMEM);
        cudaFuncSetAttribute(mma_gemm<4>, cudaFuncAttributeMaxDynamicSharedMemorySize, MMA_SMEM);
        cudaFuncSetAttribute(mma_gemm<5>, cudaFuncAttributeMaxDynamicSharedMemorySize, MMA_SMEM);
        cudaFuncSetAttribute(scan_kernel, cudaFuncAttributeMaxDynamicSharedMemorySize, SCAN_SMEM);
    }

    // fork: s3 xr; s0 prep; s2 matrix powers
    cudaEventRecord(evRoot, 0);
    cudaStreamWaitEvent(s3, evRoot, 0);
    xr_kernel<<<32768, 256, 0, s3>>>(x);
    cudaEventRecord(evXr, s3);

    prep_kernel<<<2048, 256>>>(Wh, bh, Wo, bo, h0);
    cudaEventRecord(evPrep, 0);
    cudaStreamWaitEvent(s2, evPrep, 0);
    sq512<<<dim3(8, 16), 256, 0, s2>>>(whh, whh, w2, wrt + 262144);   // W2, W2^T
    sq512<<<dim3(8, 16), 256, 0, s2>>>(w2, whh, w3, wrt + 524288);    // W3, W3^T
    sq512<<<dim3(8, 16), 256, 0, s2>>>(w2, w2, w4, wct);              // W4, W4^T
    cudaEventRecord(evSq4, s2);
    sq512<<<dim3(8, 16), 256, 0, s2>>>(w4, w4, w8, wct + 262144);     // W8, W8^T
    cudaEventRecord(evSq8, s2);
    sq512<<<dim3(8, 16), 256, 0, s2>>>(w4, w8, w12, wct + 524288);    // W12, W12^T
    sq512<<<dim3(8, 16), 256, 0, s2>>>(w8, w8, w16, wct + 786432);    // W16, W16^T
    cudaEventRecord(evSqAll, s2);

    // main chain on s0
    cudaStreamWaitEvent(0, evXr, 0);
    // G1: preh[t*256+b] = rna(xr[b][t] @ W_hx + b_h)
    mma_gemm<0><<<dim3(4, 512), 256, MMA_SMEM>>>(xr, nullptr, 1, 0, nullptr, 0, 0,
                                                 preh, w1t, bhp, 1);
    // Horner: R1 = preh(0)@W + preh(1); R2 = R1@W + preh(2); Q4 = R2@W + preh(3)
    mma_gemm<2><<<dim3(4, 128), 256, MMA_SMEM>>>(preh, nullptr, 2, 0, preh, 2, 1,
                                                 q1, wrt, nullptr, 1);
    mma_gemm<2><<<dim3(4, 128), 256, MMA_SMEM>>>(q1, nullptr, 0, 0, preh, 2, 2,
                                                 q2, wrt, nullptr, 1);
    mma_gemm<2><<<dim3(4, 128), 256, MMA_SMEM>>>(q2, nullptr, 0, 0, preh, 2, 3,
                                                 q0, wrt, nullptr, 1);
    // Q8 = Q4[2k]@W4 + Q4[2k+1] (fp32) — needs W4
    cudaStreamWaitEvent(0, evSq4, 0);
    mma_gemm<2><<<dim3(4, 64), 256, MMA_SMEM>>>(q0, nullptr, 3, 0, q0, 3, 1,
                                                q3, wct, nullptr, 0);
    // QC: Q12 = Q8[2k]@W4 + Q4[4k+2]; Q16 = Q8[2k]@W8 + Q8[2k+1] — needs W4,W8
    cudaStreamWaitEvent(0, evSq8, 0);
    mma_gemm<5><<<dim3(8, 32), 256, MMA_SMEM>>>(q3, nullptr, 3, 0, nullptr, 0, 0,
                                                nullptr, wct, nullptr, 0);
    // persistent scan (16 supersteps) — needs W12,W16
    cudaStreamWaitEvent(0, evSqAll, 0);
    scan_kernel<<<dim3(16, 8), 256, SCAN_SMEM>>>(q0, q3, out);
    // fused recovery: Hall[4j+i] = rna(Hall[4j]@W^i + {preh(4j), R1, R2})
    mma_gemm<4><<<dim3(12, 128), 256, MMA_SMEM>>>(hall, nullptr, 2, 0, nullptr, 0, 0,
                                                  nullptr, wrt, nullptr, 1);
    // G2: out[b*256+t] = sigmoid([xr | Hall-gather] @ W_o + b_o)
    mma_gemm<1><<<dim3(4, 512), 256, MMA_SMEM>>>(xr, hall, 0, 0, nullptr, 0, 0,
                                                 out, wot, bop, 0);
}